// round 12
// baseline (speedup 1.0000x reference)
#include <cuda_runtime.h>
#include <math.h>
#include <stdint.h>

// Problem constants
#define NB_  2
#define NS   1024
#define ND   1024
#define NH   16
#define NDH  64
#define NL   12
#define NHID 2816
#define NV   50257
#define NVP  50304   // padded LM-head N (128*393)
#define MTOK 2048    // NB_*NS

// GEMM tiling: 128x128 block, BK=16, 8 warps (4m x 2n), warp tile 32x64
#define BM 128
#define BN 128
#define BK 16
#define STAGE_BYTES 16384
#define NSTAGE 4
#define SMEM_BYTES (NSTAGE * STAGE_BYTES)

// ---------------- activation scratch ----------------
__device__ float    g_x[MTOK * ND];            // residual (fp32)
__device__ uint16_t g_hh[MTOK * ND];           // rmsnorm out hi
__device__ uint16_t g_hl[MTOK * ND];           // rmsnorm out lo
__device__ float    g_qkv[MTOK * 3 * ND];      // qkv (fp32)
__device__ uint16_t g_yh[MTOK * ND];           // attn out hi
__device__ uint16_t g_yl[MTOK * ND];           // attn out lo
__device__ float    g_gate[MTOK * NHID];       // gate pre-act (fp32)
__device__ uint16_t g_sh[MTOK * NHID];         // swiglu out hi
__device__ uint16_t g_sl[MTOK * NHID];         // swiglu out lo

// ---------------- weight bf16 hi/lo ----------------
__device__ uint16_t g_wqkv_h[NL * ND * 3 * ND];
__device__ uint16_t g_wqkv_l[NL * ND * 3 * ND];
__device__ uint16_t g_wproj_h[NL * ND * ND];
__device__ uint16_t g_wproj_l[NL * ND * ND];
__device__ uint16_t g_wg_h[NL * ND * NHID];
__device__ uint16_t g_wg_l[NL * ND * NHID];
__device__ uint16_t g_wu_h[NL * ND * NHID];
__device__ uint16_t g_wu_l[NL * ND * NHID];
__device__ uint16_t g_wd_h[NL * NHID * ND];
__device__ uint16_t g_wd_l[NL * NHID * ND];
__device__ uint16_t g_wlm_h[ND * NVP];
__device__ uint16_t g_wlm_l[ND * NVP];

// ---------------- helpers ----------------
// A tile smem: 128 rows x 16 bf16 (32B/row), chunk-swizzled for LDSM
__device__ __forceinline__ uint32_t a_off(int m, int k) {
    uint32_t chunk = ((uint32_t)(k >> 3) ^ ((uint32_t)(m >> 2) & 1u)) & 1u;
    return (uint32_t)m * 32u + chunk * 16u + (uint32_t)(k & 7) * 2u;
}
// B tile smem: 16 rows x 128 bf16 (256B/row), chunk-swizzled for LDSM.trans
__device__ __forceinline__ uint32_t b_off(int k, int n) {
    uint32_t nb = (uint32_t)(n >> 3);
    uint32_t chunk = (nb & 8u) | ((nb ^ ((uint32_t)k & 7u)) & 7u);
    return (uint32_t)k * 256u + chunk * 16u + (uint32_t)(n & 7) * 2u;
}

__device__ __forceinline__ void ldsm4(uint32_t* r, uint32_t addr) {
    asm volatile("ldmatrix.sync.aligned.m8n8.x4.shared.b16 {%0,%1,%2,%3}, [%4];"
        : "=r"(r[0]), "=r"(r[1]), "=r"(r[2]), "=r"(r[3]) : "r"(addr));
}
__device__ __forceinline__ void ldsm4t(uint32_t* r, uint32_t addr) {
    asm volatile("ldmatrix.sync.aligned.m8n8.x4.trans.shared.b16 {%0,%1,%2,%3}, [%4];"
        : "=r"(r[0]), "=r"(r[1]), "=r"(r[2]), "=r"(r[3]) : "r"(addr));
}
#define MMA_BF16(acc, a, b0, b1)                                              \
    asm volatile(                                                              \
        "mma.sync.aligned.m16n8k16.row.col.f32.bf16.bf16.f32 "                 \
        "{%0,%1,%2,%3}, {%4,%5,%6,%7}, {%8,%9}, {%0,%1,%2,%3};"                \
        : "+f"(acc[0]), "+f"(acc[1]), "+f"(acc[2]), "+f"(acc[3])               \
        : "r"(a[0]), "r"(a[1]), "r"(a[2]), "r"(a[3]), "r"(b0), "r"(b1))

#define CPASYNC16(dst, src)                                                    \
    asm volatile("cp.async.cg.shared.global [%0], [%1], 16;"                   \
                 :: "r"(dst), "l"(src))

// split float4 into bf16x4 hi (rn) + lo (rn of residual)
__device__ __forceinline__ void split4(float4 v, uint2& hi, uint2& lo) {
    uint32_t h0, h1, l0, l1;
    asm("cvt.rn.bf16x2.f32 %0, %1, %2;" : "=r"(h0) : "f"(v.y), "f"(v.x));
    asm("cvt.rn.bf16x2.f32 %0, %1, %2;" : "=r"(h1) : "f"(v.w), "f"(v.z));
    float hx = __uint_as_float(h0 << 16);
    float hy = __uint_as_float(h0 & 0xffff0000u);
    float hz = __uint_as_float(h1 << 16);
    float hw = __uint_as_float(h1 & 0xffff0000u);
    float lx = v.x - hx, ly = v.y - hy, lz = v.z - hz, lw = v.w - hw;
    asm("cvt.rn.bf16x2.f32 %0, %1, %2;" : "=r"(l0) : "f"(ly), "f"(lx));
    asm("cvt.rn.bf16x2.f32 %0, %1, %2;" : "=r"(l1) : "f"(lw), "f"(lz));
    hi.x = h0; hi.y = h1; lo.x = l0; lo.y = l1;
}
// split pair (a=elem0, b=elem1) into hi/lo bf16x2 words
__device__ __forceinline__ void split2(float a, float b, uint32_t& h, uint32_t& l) {
    asm("cvt.rn.bf16x2.f32 %0, %1, %2;" : "=r"(h) : "f"(b), "f"(a));
    float ha = __uint_as_float(h << 16);
    float hb = __uint_as_float(h & 0xffff0000u);
    asm("cvt.rn.bf16x2.f32 %0, %1, %2;" : "=r"(l) : "f"(b - hb), "f"(a - ha));
}

// ---------------- weight split kernels ----------------
__global__ void wsplit_kernel(const float* __restrict__ w,
                              uint16_t* __restrict__ wh,
                              uint16_t* __restrict__ wl, int n4) {
    int i = blockIdx.x * 256 + threadIdx.x;
    if (i < n4) {
        float4 v = ((const float4*)w)[i];
        uint2 hi, lo;
        split4(v, hi, lo);
        ((uint2*)wh)[i] = hi;
        ((uint2*)wl)[i] = lo;
    }
}
// LM head: pad [1024,50257] -> [1024,50304] with zeros
__global__ void wsplit_pad_kernel(const float* __restrict__ w,
                                  uint16_t* __restrict__ wh,
                                  uint16_t* __restrict__ wl) {
    int c = blockIdx.x * 256 + threadIdx.x;
    int r = blockIdx.y;
    if (c < NVP) {
        float x = (c < NV) ? w[(size_t)r * NV + c] : 0.0f;
        uint32_t h, l;
        split2(x, 0.0f, h, l);
        wh[(size_t)r * NVP + c] = (uint16_t)(h & 0xffffu);
        wl[(size_t)r * NVP + c] = (uint16_t)(l & 0xffffu);
    }
}

// ---------------- embedding ----------------
__global__ void embed_kernel(const int* __restrict__ idx,
                             const float* __restrict__ wte,
                             const float* __restrict__ wpe,
                             float* __restrict__ x) {
    int row = blockIdx.x;
    int t = threadIdx.x;
    int tok = idx[row];
    int spos = row & (NS - 1);
    float4 a = ((const float4*)(wte + (size_t)tok * ND))[t];
    float4 b = ((const float4*)(wpe + (size_t)spos * ND))[t];
    float4 o;
    o.x = a.x + b.x; o.y = a.y + b.y; o.z = a.z + b.z; o.w = a.w + b.w;
    ((float4*)(x + (size_t)row * ND))[t] = o;
}

// ---------------- rmsnorm -> bf16 hi/lo ----------------
__global__ void rmsnorm_hl_kernel(const float* __restrict__ in,
                                  const float* __restrict__ gamma,
                                  uint16_t* __restrict__ oh,
                                  uint16_t* __restrict__ ol) {
    int row = blockIdx.x;
    int t = threadIdx.x;
    float4 v = ((const float4*)(in + (size_t)row * ND))[t];
    float ss = v.x * v.x + v.y * v.y + v.z * v.z + v.w * v.w;
    #pragma unroll
    for (int off = 16; off; off >>= 1)
        ss += __shfl_xor_sync(0xFFFFFFFFu, ss, off);
    __shared__ float red[8];
    if ((t & 31) == 0) red[t >> 5] = ss;
    __syncthreads();
    float tot = red[0] + red[1] + red[2] + red[3] +
                red[4] + red[5] + red[6] + red[7];
    float r = rsqrtf(tot * (1.0f / (float)ND) + 1e-12f);
    float4 g = ((const float4*)gamma)[t];
    float4 o;
    o.x = v.x * r * g.x; o.y = v.y * r * g.y;
    o.z = v.z * r * g.z; o.w = v.w * r * g.w;
    uint2 hi, lo;
    split4(o, hi, lo);
    ((uint2*)oh)[row * 256 + t] = hi;
    ((uint2*)ol)[row * 256 + t] = lo;
}

// ---------------- bf16 tensor-core GEMM, cp.async 4-stage ------------------
// C[M,N] = epi(A[M,K] @ B[K,N]) with A,B given as bf16 hi/lo pairs.
// EPI 0: C = acc (fp32) ; EPI 1: C = X + acc (fp32) ; EPI 2: silu(X)*acc
// OUTHL: write result as bf16 hi/lo to Oh/Ol instead of fp32 C.
// NBs = B row stride (may exceed N for padded LM head); C/X stride = N.
// NOTE: fp32 stores use scalar path when N is odd (LM head) — alignment.
template<int EPI, bool OUTHL>
__global__ __launch_bounds__(256, 2)
void gemm_bf(const uint16_t* __restrict__ Ah, const uint16_t* __restrict__ Al,
             const uint16_t* __restrict__ Bh, const uint16_t* __restrict__ Bl,
             const float* __restrict__ X, float* __restrict__ C,
             uint16_t* __restrict__ Oh, uint16_t* __restrict__ Ol,
             int M, int N, int NBs, int K) {
    extern __shared__ __align__(16) char sm[];
    const uint32_t sb = (uint32_t)__cvta_generic_to_shared(sm);

    const int tid  = threadIdx.x;
    const int lane = tid & 31;
    const int warp = tid >> 5;
    const int wm = warp & 3;        // 0..3
    const int wn = warp >> 2;       // 0..1
    const int lq = lane >> 2;       // 0..7
    const int lr = lane & 3;        // 0..3
    const int m0 = blockIdx.y * BM;
    const int n0 = blockIdx.x * BN;

    float c[2][8][4];
    #pragma unroll
    for (int i = 0; i < 2; i++)
        #pragma unroll
        for (int j = 0; j < 8; j++)
            #pragma unroll
            for (int k = 0; k < 4; k++) c[i][j][k] = 0.0f;

    // per-thread load slots (256 threads):
    // A: 128 rows x 2 chunks of 8 bf16 : m = tid>>1, kc = (tid&1)*8
    // B: 16 rows x 16 chunks           : k = tid>>4, nc = (tid&15)*8
    const int am = tid >> 1;
    const int ak = (tid & 1) * 8;
    const int bk = tid >> 4;
    const int bn = (tid & 15) * 8;
    const uint32_t a_dst = a_off(am, ak);
    const uint32_t b_dst = b_off(bk, bn);

    auto issue = [&](int kt) {
        const int kbase = kt * BK;
        const uint32_t stg = sb + (uint32_t)(kt & 3) * (uint32_t)STAGE_BYTES;
        const uint16_t* sa = Ah + (size_t)(m0 + am) * K + kbase + ak;
        const uint16_t* sa2 = Al + (size_t)(m0 + am) * K + kbase + ak;
        CPASYNC16(stg + a_dst, sa);
        CPASYNC16(stg + 4096u + a_dst, sa2);
        const uint16_t* sbh = Bh + (size_t)(kbase + bk) * NBs + n0 + bn;
        const uint16_t* sbl = Bl + (size_t)(kbase + bk) * NBs + n0 + bn;
        CPASYNC16(stg + 8192u + b_dst, sbh);
        CPASYNC16(stg + 12288u + b_dst, sbl);
        asm volatile("cp.async.commit_group;" ::: "memory");
    };

    const int lid8 = lane >> 3;      // matrix id 0..3
    const int lrow = lane & 7;       // row within matrix

    auto compute = [&](int buf) {
        const uint32_t ah_base = sb + (uint32_t)buf * (uint32_t)STAGE_BYTES;
        const uint32_t al_base = ah_base + 4096u;
        const uint32_t bh_base = ah_base + 8192u;
        const uint32_t bl_base = ah_base + 12288u;

        uint32_t ah[2][4], al[2][4];
        {
            int m = ((lid8 & 1) << 3) + lrow;
            int k = (lid8 >> 1) << 3;
            #pragma unroll
            for (int mf = 0; mf < 2; mf++) {
                uint32_t off = a_off(wm * 32 + mf * 16 + m, k);
                ldsm4(ah[mf], ah_base + off);
                ldsm4(al[mf], al_base + off);
            }
        }
        #pragma unroll
        for (int h = 0; h < 2; h++) {
            uint32_t bhf[4][2], blf[4][2];
            #pragma unroll
            for (int j = 0; j < 2; j++) {
                int k  = ((lid8 & 1) << 3) + lrow;
                int nb = wn * 8 + h * 4 + j * 2 + (lid8 >> 1);
                uint32_t off = b_off(k, nb << 3);
                uint32_t rr[4];
                ldsm4t(rr, bh_base + off);
                bhf[j * 2][0] = rr[0]; bhf[j * 2][1] = rr[1];
                bhf[j * 2 + 1][0] = rr[2]; bhf[j * 2 + 1][1] = rr[3];
                ldsm4t(rr, bl_base + off);
                blf[j * 2][0] = rr[0]; blf[j * 2][1] = rr[1];
                blf[j * 2 + 1][0] = rr[2]; blf[j * 2 + 1][1] = rr[3];
            }
            #pragma unroll
            for (int mf = 0; mf < 2; mf++)
                #pragma unroll
                for (int j = 0; j < 4; j++) {
                    int nf = h * 4 + j;
                    MMA_BF16(c[mf][nf], ah[mf], bhf[j][0], bhf[j][1]);
                    MMA_BF16(c[mf][nf], ah[mf], blf[j][0], blf[j][1]);
                    MMA_BF16(c[mf][nf], al[mf], bhf[j][0], bhf[j][1]);
                }
        }
    };

    // ---- main loop: 4-stage cp.async pipeline ----
    const int ntk = K / BK;
    issue(0); issue(1); issue(2);
    for (int kt = 0; kt < ntk; kt++) {
        asm volatile("cp.async.wait_group 2;" ::: "memory");
        __syncthreads();
        compute(kt & 3);
        if (kt + 3 < ntk) issue(kt + 3);
        else asm volatile("cp.async.commit_group;" ::: "memory");
    }

    // ---- epilogue ----
    const bool evenN = ((N & 1) == 0);
    #pragma unroll
    for (int mf = 0; mf < 2; mf++) {
        int r0 = m0 + wm * 32 + mf * 16 + lq;
        int r1 = r0 + 8;
        #pragma unroll
        for (int nf = 0; nf < 8; nf++) {
            int col = n0 + wn * 64 + nf * 8 + 2 * lr;
            size_t o0 = (size_t)r0 * N + col;
            size_t o1 = (size_t)r1 * N + col;
            float2 v0 = make_float2(c[mf][nf][0], c[mf][nf][1]);
            float2 v1 = make_float2(c[mf][nf][2], c[mf][nf][3]);
            if (col + 2 <= N) {
                if (EPI == 1) {
                    float2 x0 = *(const float2*)(X + o0);
                    float2 x1 = *(const float2*)(X + o1);
                    v0.x += x0.x; v0.y += x0.y; v1.x += x1.x; v1.y += x1.y;
                } else if (EPI == 2) {
                    float2 x0 = *(const float2*)(X + o0);
                    float2 x1 = *(const float2*)(X + o1);
                    v0.x *= x0.x / (1.0f + __expf(-x0.x));
                    v0.y *= x0.y / (1.0f + __expf(-x0.y));
                    v1.x *= x1.x / (1.0f + __expf(-x1.x));
                    v1.y *= x1.y / (1.0f + __expf(-x1.y));
                }
                if (OUTHL) {
                    uint32_t h0, l0, h1, l1;
                    split2(v0.x, v0.y, h0, l0);
                    split2(v1.x, v1.y, h1, l1);
                    *(uint32_t*)(Oh + o0) = h0;
                    *(uint32_t*)(Ol + o0) = l0;
                    *(uint32_t*)(Oh + o1) = h1;
                    *(uint32_t*)(Ol + o1) = l1;
                } else if (evenN) {
                    *(float2*)(C + o0) = v0;
                    *(float2*)(C + o1) = v1;
                } else {
                    // odd N (LM head): row base parity varies -> scalar stores
                    C[o0] = v0.x; C[o0 + 1] = v0.y;
                    C[o1] = v1.x; C[o1 + 1] = v1.y;
                }
            } else if (col < N) {
                float a0 = v0.x, a1 = v1.x;
                if (EPI == 1) { a0 += X[o0]; a1 += X[o1]; }
                else if (EPI == 2) {
                    float x0 = X[o0], x1 = X[o1];
                    a0 *= x0 / (1.0f + __expf(-x0));
                    a1 *= x1 / (1.0f + __expf(-x1));
                }
                C[o0] = a0; C[o1] = a1;
            }
        }
    }
}

// ---------------- flash attention v3 (causal, fp32, 4 threads/row) --------
// grid (NB_*NH, NS/64), block 256: 64 q-rows, 4 threads per row.
// Thread quarter qd owns dims {i*16 + qd*4 .. +3} for i in 0..3.
// Output written as bf16 hi/lo.
__global__ __launch_bounds__(256)
void attn_kernel(const float* __restrict__ qkv,
                 uint16_t* __restrict__ yh, uint16_t* __restrict__ yl) {
    const int bh = blockIdx.x;
    const int b  = bh >> 4;
    const int hd = bh & 15;
    const int qg = blockIdx.y;            // 0..15
    const int tid = threadIdx.x;          // 0..255
    const int row = tid >> 2;             // 0..63
    const int qd  = tid & 3;
    const int qrow = qg * 64 + row;
    const int doff = qd * 4;

    const float* qptr = qkv + ((size_t)(b * NS + qrow) * (3 * ND)) + hd * NDH;
    float4 q[4];
    #pragma unroll
    for (int i = 0; i < 4; i++)
        q[i] = *(const float4*)(qptr + i * 16 + doff);

    float4 o[4];
    #pragma unroll
    for (int i = 0; i < 4; i++) o[i] = make_float4(0.f, 0.f, 0.f, 0.f);
    float m = -1e30f, l = 0.0f;

    __shared__ float ksm[64][64];
    __shared__ float vsm[64][64];

    const int ntiles = qg + 1;
    for (int kt = 0; kt < ntiles; kt++) {
        const int kbase = kt * 64;
        #pragma unroll
        for (int i = 0; i < 4; i++) {
            int li = tid + i * 256;
            int r  = li >> 4;
            int c4 = (li & 15) * 4;
            const float* base = qkv + ((size_t)(b * NS + kbase + r) * (3 * ND))
                                + hd * NDH + c4;
            *(float4*)&ksm[r][c4] = *(const float4*)(base + ND);
            *(float4*)&vsm[r][c4] = *(const float4*)(base + 2 * ND);
        }
        __syncthreads();

        #pragma unroll 1
        for (int jt = 0; jt < 4; jt++) {
            float s[16];
            #pragma unroll
            for (int j = 0; j < 16; j++) {
                int jr = jt * 16 + j;
                float a = 0.0f;
                #pragma unroll
                for (int i = 0; i < 4; i++) {
                    float4 kv = *(const float4*)&ksm[jr][i * 16 + doff];
                    a += q[i].x * kv.x + q[i].y * kv.y
                       + q[i].z * kv.z + q[i].w * kv.w;
                }
                a += __shfl_xor_sync(0xFFFFFFFFu, a, 1);
                a += __shfl_xor_sync(0xFFFFFFFFu, a, 2);
                int key = kbase + jr;
                s[j] = (key <= qrow) ? a * 0.125f : -1e30f;
            }
            float tm = s[0];
            #pragma unroll
            for (int j = 1; j < 16; j++) tm = fmaxf(tm, s[j]);
            float mnew = fmaxf(m, tm);
            float corr = __expf(m - mnew);
            float psum = 0.0f;
            #pragma unroll
            for (int j = 0; j < 16; j++) {
                s[j] = __expf(s[j] - mnew);
                psum += s[j];
            }
            l = l * corr + psum;
            m = mnew;
            #pragma unroll
            for (int i = 0; i < 4; i++) {
                o[i].x *= corr; o[i].y *= corr; o[i].z *= corr; o[i].w *= corr;
            }
            #pragma unroll
            for (int j = 0; j < 16; j++) {
                float p = s[j];
                int jr = jt * 16 + j;
                #pragma unroll
                for (int i = 0; i < 4; i++) {
                    float4 vv = *(const float4*)&vsm[jr][i * 16 + doff];
                    o[i].x += p * vv.x; o[i].y += p * vv.y;
                    o[i].z += p * vv.z; o[i].w += p * vv.w;
                }
            }
        }
        __syncthreads();
    }

    float inv = 1.0f / l;
    size_t base = (size_t)(b * NS + qrow) * ND + hd * NDH;
    #pragma unroll
    for (int i = 0; i < 4; i++) {
        float4 st;
        st.x = o[i].x * inv; st.y = o[i].y * inv;
        st.z = o[i].z * inv; st.w = o[i].w * inv;
        uint2 hi, lo;
        split4(st, hi, lo);
        size_t eo = base + i * 16 + doff;
        *(uint2*)(yh + eo) = hi;
        *(uint2*)(yl + eo) = lo;
    }
}

// ---------------- launch ----------------
extern "C" void kernel_launch(void* const* d_in, const int* in_sizes, int n_in,
                              void* d_out, int out_size) {
    const int*   idx   = (const int*)  d_in[0];
    const float* wte   = (const float*)d_in[1];
    const float* wpe   = (const float*)d_in[2];
    const float* g1    = (const float*)d_in[3];
    const float* Wqkv  = (const float*)d_in[4];
    const float* Wproj = (const float*)d_in[5];
    const float* g2    = (const float*)d_in[6];
    const float* Wg    = (const float*)d_in[7];
    const float* Wu    = (const float*)d_in[8];
    const float* Wd    = (const float*)d_in[9];
    const float* gf    = (const float*)d_in[10];
    const float* Wlm   = (const float*)d_in[11];
    float* out = (float*)d_out;

    float *px, *pqkv, *pgate;
    uint16_t *phh, *phl, *pyh, *pyl, *psh, *psl;
    uint16_t *wqh, *wql, *wph, *wpl, *wgh, *wgl, *wuh, *wul, *wdh, *wdl, *wlh, *wll;
    cudaGetSymbolAddress((void**)&px,    g_x);
    cudaGetSymbolAddress((void**)&pqkv,  g_qkv);
    cudaGetSymbolAddress((void**)&pgate, g_gate);
    cudaGetSymbolAddress((void**)&phh,   g_hh);
    cudaGetSymbolAddress((void**)&phl,   g_hl);
    cudaGetSymbolAddress((void**)&pyh,   g_yh);
    cudaGetSymbolAddress((void**)&pyl,   g_yl);
    cudaGetSymbolAddress((void**)&psh,   g_sh);
    cudaGetSymbolAddress((void**)&psl,   g_sl);
    cudaGetSymbolAddress((void**)&wqh,   g_wqkv_h);
    cudaGetSymbolAddress((void**)&wql,   g_wqkv_l);
    cudaGetSymbolAddress((void**)&wph,   g_wproj_h);
    cudaGetSymbolAddress((void**)&wpl,   g_wproj_l);
    cudaGetSymbolAddress((void**)&wgh,   g_wg_h);
    cudaGetSymbolAddress((void**)&wgl,   g_wg_l);
    cudaGetSymbolAddress((void**)&wuh,   g_wu_h);
    cudaGetSymbolAddress((void**)&wul,   g_wu_l);
    cudaGetSymbolAddress((void**)&wdh,   g_wd_h);
    cudaGetSymbolAddress((void**)&wdl,   g_wd_l);
    cudaGetSymbolAddress((void**)&wlh,   g_wlm_h);
    cudaGetSymbolAddress((void**)&wll,   g_wlm_l);

    cudaFuncSetAttribute(gemm_bf<0, false>,
        cudaFuncAttributeMaxDynamicSharedMemorySize, SMEM_BYTES);
    cudaFuncSetAttribute(gemm_bf<1, false>,
        cudaFuncAttributeMaxDynamicSharedMemorySize, SMEM_BYTES);
    cudaFuncSetAttribute(gemm_bf<2, true>,
        cudaFuncAttributeMaxDynamicSharedMemorySize, SMEM_BYTES);

    // ---- weight split (runs each call) ----
    {
        int n4;
        n4 = NL * ND * 3 * ND / 4;
        wsplit_kernel<<<(n4 + 255) / 256, 256>>>(Wqkv, wqh, wql, n4);
        n4 = NL * ND * ND / 4;
        wsplit_kernel<<<(n4 + 255) / 256, 256>>>(Wproj, wph, wpl, n4);
        n4 = NL * ND * NHID / 4;
        wsplit_kernel<<<(n4 + 255) / 256, 256>>>(Wg, wgh, wgl, n4);
        wsplit_kernel<<<(n4 + 255) / 256, 256>>>(Wu, wuh, wul, n4);
        n4 = NL * NHID * ND / 4;
        wsplit_kernel<<<(n4 + 255) / 256, 256>>>(Wd, wdh, wdl, n4);
        wsplit_pad_kernel<<<dim3((NVP + 255) / 256, ND), 256>>>(Wlm, wlh, wll);
    }

    embed_kernel<<<MTOK, 256>>>(idx, wte, wpe, px);

    for (int l = 0; l < NL; l++) {
        rmsnorm_hl_kernel<<<MTOK, 256>>>(px, g1 + (size_t)l * ND, phh, phl);
        gemm_bf<0, false><<<dim3(3 * ND / BN, MTOK / BM), 256, SMEM_BYTES>>>(
            phh, phl, wqh + (size_t)l * ND * 3 * ND, wql + (size_t)l * ND * 3 * ND,
            nullptr, pqkv, nullptr, nullptr, MTOK, 3 * ND, 3 * ND, ND);
        attn_kernel<<<dim3(NB_ * NH, NS / 64), 256>>>(pqkv, pyh, pyl);
        gemm_bf<1, false><<<dim3(ND / BN, MTOK / BM), 256, SMEM_BYTES>>>(
            pyh, pyl, wph + (size_t)l * ND * ND, wpl + (size_t)l * ND * ND,
            px, px, nullptr, nullptr, MTOK, ND, ND, ND);
        rmsnorm_hl_kernel<<<MTOK, 256>>>(px, g2 + (size_t)l * ND, phh, phl);
        gemm_bf<0, false><<<dim3(NHID / BN, MTOK / BM), 256, SMEM_BYTES>>>(
            phh, phl, wgh + (size_t)l * ND * NHID, wgl + (size_t)l * ND * NHID,
            nullptr, pgate, nullptr, nullptr, MTOK, NHID, NHID, ND);
        gemm_bf<2, true><<<dim3(NHID / BN, MTOK / BM), 256, SMEM_BYTES>>>(
            phh, phl, wuh + (size_t)l * ND * NHID, wul + (size_t)l * ND * NHID,
            pgate, nullptr, psh, psl, MTOK, NHID, NHID, ND);
        gemm_bf<1, false><<<dim3(ND / BN, MTOK / BM), 256, SMEM_BYTES>>>(
            psh, psl, wdh + (size_t)l * NHID * ND, wdl + (size_t)l * NHID * ND,
            px, px, nullptr, nullptr, MTOK, ND, ND, NHID);
    }

    rmsnorm_hl_kernel<<<MTOK, 256>>>(px, gf, phh, phl);
    gemm_bf<0, false><<<dim3(NVP / BN, MTOK / BM), 256, SMEM_BYTES>>>(
        phh, phl, wlh, wll, nullptr, out, nullptr, nullptr, MTOK, NV, NVP, ND);
}

// round 13
// speedup vs baseline: 1.2292x; 1.2292x over previous
#include <cuda_runtime.h>
#include <math.h>
#include <stdint.h>

// Problem constants
#define NB_  2
#define NS   1024
#define ND   1024
#define NH   16
#define NDH  64
#define NL   12
#define NHID 2816
#define NV   50257
#define NVP  50304   // padded LM-head N (128*393)
#define MTOK 2048    // NB_*NS

// GEMM tiling: 128x128 block, BK=16, 8 warps (4m x 2n), warp tile 32x64
#define BM 128
#define BN 128
#define BK 16
#define STAGE_BYTES 16384
#define NSTAGE 4
#define SMEM_BYTES (NSTAGE * STAGE_BYTES)

// ---------------- activation scratch ----------------
__device__ float    g_x[MTOK * ND];            // residual (fp32)
__device__ uint16_t g_hh[MTOK * ND];           // rmsnorm out hi
__device__ uint16_t g_hl[MTOK * ND];           // rmsnorm out lo
__device__ float    g_qkv[MTOK * 3 * ND];      // qkv (fp32)
__device__ uint16_t g_yh[MTOK * ND];           // attn out hi
__device__ uint16_t g_yl[MTOK * ND];           // attn out lo
__device__ float    g_gate[MTOK * NHID];       // gate pre-act (fp32)
__device__ uint16_t g_sh[MTOK * NHID];         // swiglu out hi
__device__ uint16_t g_sl[MTOK * NHID];         // swiglu out lo
// split-KV attention partials (2 halves)
__device__ float    g_po[2 * MTOK * ND];       // unnormalized o
__device__ float    g_pm[2 * MTOK * NH];       // running max
__device__ float    g_pl[2 * MTOK * NH];       // running sum

// ---------------- weight bf16 hi/lo ----------------
__device__ uint16_t g_wqkv_h[NL * ND * 3 * ND];
__device__ uint16_t g_wqkv_l[NL * ND * 3 * ND];
__device__ uint16_t g_wproj_h[NL * ND * ND];
__device__ uint16_t g_wproj_l[NL * ND * ND];
__device__ uint16_t g_wg_h[NL * ND * NHID];
__device__ uint16_t g_wg_l[NL * ND * NHID];
__device__ uint16_t g_wu_h[NL * ND * NHID];
__device__ uint16_t g_wu_l[NL * ND * NHID];
__device__ uint16_t g_wd_h[NL * NHID * ND];
__device__ uint16_t g_wd_l[NL * NHID * ND];
__device__ uint16_t g_wlm_h[ND * NVP];
__device__ uint16_t g_wlm_l[ND * NVP];

// ---------------- helpers ----------------
// A tile smem: 128 rows x 16 bf16 (32B/row), chunk-swizzled for LDSM
__device__ __forceinline__ uint32_t a_off(int m, int k) {
    uint32_t chunk = ((uint32_t)(k >> 3) ^ ((uint32_t)(m >> 2) & 1u)) & 1u;
    return (uint32_t)m * 32u + chunk * 16u + (uint32_t)(k & 7) * 2u;
}
// B tile smem: 16 rows x 128 bf16 (256B/row), chunk-swizzled for LDSM.trans
__device__ __forceinline__ uint32_t b_off(int k, int n) {
    uint32_t nb = (uint32_t)(n >> 3);
    uint32_t chunk = (nb & 8u) | ((nb ^ ((uint32_t)k & 7u)) & 7u);
    return (uint32_t)k * 256u + chunk * 16u + (uint32_t)(n & 7) * 2u;
}

__device__ __forceinline__ void ldsm4(uint32_t* r, uint32_t addr) {
    asm volatile("ldmatrix.sync.aligned.m8n8.x4.shared.b16 {%0,%1,%2,%3}, [%4];"
        : "=r"(r[0]), "=r"(r[1]), "=r"(r[2]), "=r"(r[3]) : "r"(addr));
}
__device__ __forceinline__ void ldsm4t(uint32_t* r, uint32_t addr) {
    asm volatile("ldmatrix.sync.aligned.m8n8.x4.trans.shared.b16 {%0,%1,%2,%3}, [%4];"
        : "=r"(r[0]), "=r"(r[1]), "=r"(r[2]), "=r"(r[3]) : "r"(addr));
}
#define MMA_BF16(acc, a, b0, b1)                                              \
    asm volatile(                                                              \
        "mma.sync.aligned.m16n8k16.row.col.f32.bf16.bf16.f32 "                 \
        "{%0,%1,%2,%3}, {%4,%5,%6,%7}, {%8,%9}, {%0,%1,%2,%3};"                \
        : "+f"(acc[0]), "+f"(acc[1]), "+f"(acc[2]), "+f"(acc[3])               \
        : "r"(a[0]), "r"(a[1]), "r"(a[2]), "r"(a[3]), "r"(b0), "r"(b1))

#define CPASYNC16(dst, src)                                                    \
    asm volatile("cp.async.cg.shared.global [%0], [%1], 16;"                   \
                 :: "r"(dst), "l"(src))

// split float4 into bf16x4 hi (rn) + lo (rn of residual)
__device__ __forceinline__ void split4(float4 v, uint2& hi, uint2& lo) {
    uint32_t h0, h1, l0, l1;
    asm("cvt.rn.bf16x2.f32 %0, %1, %2;" : "=r"(h0) : "f"(v.y), "f"(v.x));
    asm("cvt.rn.bf16x2.f32 %0, %1, %2;" : "=r"(h1) : "f"(v.w), "f"(v.z));
    float hx = __uint_as_float(h0 << 16);
    float hy = __uint_as_float(h0 & 0xffff0000u);
    float hz = __uint_as_float(h1 << 16);
    float hw = __uint_as_float(h1 & 0xffff0000u);
    float lx = v.x - hx, ly = v.y - hy, lz = v.z - hz, lw = v.w - hw;
    asm("cvt.rn.bf16x2.f32 %0, %1, %2;" : "=r"(l0) : "f"(ly), "f"(lx));
    asm("cvt.rn.bf16x2.f32 %0, %1, %2;" : "=r"(l1) : "f"(lw), "f"(lz));
    hi.x = h0; hi.y = h1; lo.x = l0; lo.y = l1;
}
// split pair (a=elem0, b=elem1) into hi/lo bf16x2 words
__device__ __forceinline__ void split2(float a, float b, uint32_t& h, uint32_t& l) {
    asm("cvt.rn.bf16x2.f32 %0, %1, %2;" : "=r"(h) : "f"(b), "f"(a));
    float ha = __uint_as_float(h << 16);
    float hb = __uint_as_float(h & 0xffff0000u);
    asm("cvt.rn.bf16x2.f32 %0, %1, %2;" : "=r"(l) : "f"(b - hb), "f"(a - ha));
}

// ---------------- weight split kernels ----------------
__global__ void wsplit_kernel(const float* __restrict__ w,
                              uint16_t* __restrict__ wh,
                              uint16_t* __restrict__ wl, int n4) {
    int i = blockIdx.x * 256 + threadIdx.x;
    if (i < n4) {
        float4 v = ((const float4*)w)[i];
        uint2 hi, lo;
        split4(v, hi, lo);
        ((uint2*)wh)[i] = hi;
        ((uint2*)wl)[i] = lo;
    }
}
// LM head: pad [1024,50257] -> [1024,50304] with zeros
__global__ void wsplit_pad_kernel(const float* __restrict__ w,
                                  uint16_t* __restrict__ wh,
                                  uint16_t* __restrict__ wl) {
    int c = blockIdx.x * 256 + threadIdx.x;
    int r = blockIdx.y;
    if (c < NVP) {
        float x = (c < NV) ? w[(size_t)r * NV + c] : 0.0f;
        uint32_t h, l;
        split2(x, 0.0f, h, l);
        wh[(size_t)r * NVP + c] = (uint16_t)(h & 0xffffu);
        wl[(size_t)r * NVP + c] = (uint16_t)(l & 0xffffu);
    }
}

// ---------------- embedding ----------------
__global__ void embed_kernel(const int* __restrict__ idx,
                             const float* __restrict__ wte,
                             const float* __restrict__ wpe,
                             float* __restrict__ x) {
    int row = blockIdx.x;
    int t = threadIdx.x;
    int tok = idx[row];
    int spos = row & (NS - 1);
    float4 a = ((const float4*)(wte + (size_t)tok * ND))[t];
    float4 b = ((const float4*)(wpe + (size_t)spos * ND))[t];
    float4 o;
    o.x = a.x + b.x; o.y = a.y + b.y; o.z = a.z + b.z; o.w = a.w + b.w;
    ((float4*)(x + (size_t)row * ND))[t] = o;
}

// ---------------- rmsnorm -> bf16 hi/lo ----------------
__global__ void rmsnorm_hl_kernel(const float* __restrict__ in,
                                  const float* __restrict__ gamma,
                                  uint16_t* __restrict__ oh,
                                  uint16_t* __restrict__ ol) {
    int row = blockIdx.x;
    int t = threadIdx.x;
    float4 v = ((const float4*)(in + (size_t)row * ND))[t];
    float ss = v.x * v.x + v.y * v.y + v.z * v.z + v.w * v.w;
    #pragma unroll
    for (int off = 16; off; off >>= 1)
        ss += __shfl_xor_sync(0xFFFFFFFFu, ss, off);
    __shared__ float red[8];
    if ((t & 31) == 0) red[t >> 5] = ss;
    __syncthreads();
    float tot = red[0] + red[1] + red[2] + red[3] +
                red[4] + red[5] + red[6] + red[7];
    float r = rsqrtf(tot * (1.0f / (float)ND) + 1e-12f);
    float4 g = ((const float4*)gamma)[t];
    float4 o;
    o.x = v.x * r * g.x; o.y = v.y * r * g.y;
    o.z = v.z * r * g.z; o.w = v.w * r * g.w;
    uint2 hi, lo;
    split4(o, hi, lo);
    ((uint2*)oh)[row * 256 + t] = hi;
    ((uint2*)ol)[row * 256 + t] = lo;
}

// ---------------- bf16 tensor-core GEMM, cp.async 4-stage ------------------
// C[M,N] = epi(A[M,K] @ B[K,N]) with A,B given as bf16 hi/lo pairs.
// EPI 0: C = acc (fp32) ; EPI 1: C = X + acc (fp32) ; EPI 2: silu(X)*acc
// OUTHL: write result as bf16 hi/lo to Oh/Ol instead of fp32 C.
// NBs = B row stride (may exceed N for padded LM head); C/X stride = N.
// NOTE: fp32 stores use scalar path when N is odd (LM head) — alignment.
template<int EPI, bool OUTHL>
__global__ __launch_bounds__(256, 2)
void gemm_bf(const uint16_t* __restrict__ Ah, const uint16_t* __restrict__ Al,
             const uint16_t* __restrict__ Bh, const uint16_t* __restrict__ Bl,
             const float* __restrict__ X, float* __restrict__ C,
             uint16_t* __restrict__ Oh, uint16_t* __restrict__ Ol,
             int M, int N, int NBs, int K) {
    extern __shared__ __align__(16) char sm[];
    const uint32_t sb = (uint32_t)__cvta_generic_to_shared(sm);

    const int tid  = threadIdx.x;
    const int lane = tid & 31;
    const int warp = tid >> 5;
    const int wm = warp & 3;        // 0..3
    const int wn = warp >> 2;       // 0..1
    const int lq = lane >> 2;       // 0..7
    const int lr = lane & 3;        // 0..3
    const int m0 = blockIdx.y * BM;
    const int n0 = blockIdx.x * BN;

    float c[2][8][4];
    #pragma unroll
    for (int i = 0; i < 2; i++)
        #pragma unroll
        for (int j = 0; j < 8; j++)
            #pragma unroll
            for (int k = 0; k < 4; k++) c[i][j][k] = 0.0f;

    const int am = tid >> 1;
    const int ak = (tid & 1) * 8;
    const int bk = tid >> 4;
    const int bn = (tid & 15) * 8;
    const uint32_t a_dst = a_off(am, ak);
    const uint32_t b_dst = b_off(bk, bn);

    auto issue = [&](int kt) {
        const int kbase = kt * BK;
        const uint32_t stg = sb + (uint32_t)(kt & 3) * (uint32_t)STAGE_BYTES;
        const uint16_t* sa = Ah + (size_t)(m0 + am) * K + kbase + ak;
        const uint16_t* sa2 = Al + (size_t)(m0 + am) * K + kbase + ak;
        CPASYNC16(stg + a_dst, sa);
        CPASYNC16(stg + 4096u + a_dst, sa2);
        const uint16_t* sbh = Bh + (size_t)(kbase + bk) * NBs + n0 + bn;
        const uint16_t* sbl = Bl + (size_t)(kbase + bk) * NBs + n0 + bn;
        CPASYNC16(stg + 8192u + b_dst, sbh);
        CPASYNC16(stg + 12288u + b_dst, sbl);
        asm volatile("cp.async.commit_group;" ::: "memory");
    };

    const int lid8 = lane >> 3;      // matrix id 0..3
    const int lrow = lane & 7;       // row within matrix

    auto compute = [&](int buf) {
        const uint32_t ah_base = sb + (uint32_t)buf * (uint32_t)STAGE_BYTES;
        const uint32_t al_base = ah_base + 4096u;
        const uint32_t bh_base = ah_base + 8192u;
        const uint32_t bl_base = ah_base + 12288u;

        uint32_t ah[2][4], al[2][4];
        {
            int m = ((lid8 & 1) << 3) + lrow;
            int k = (lid8 >> 1) << 3;
            #pragma unroll
            for (int mf = 0; mf < 2; mf++) {
                uint32_t off = a_off(wm * 32 + mf * 16 + m, k);
                ldsm4(ah[mf], ah_base + off);
                ldsm4(al[mf], al_base + off);
            }
        }
        #pragma unroll
        for (int h = 0; h < 2; h++) {
            uint32_t bhf[4][2], blf[4][2];
            #pragma unroll
            for (int j = 0; j < 2; j++) {
                int k  = ((lid8 & 1) << 3) + lrow;
                int nb = wn * 8 + h * 4 + j * 2 + (lid8 >> 1);
                uint32_t off = b_off(k, nb << 3);
                uint32_t rr[4];
                ldsm4t(rr, bh_base + off);
                bhf[j * 2][0] = rr[0]; bhf[j * 2][1] = rr[1];
                bhf[j * 2 + 1][0] = rr[2]; bhf[j * 2 + 1][1] = rr[3];
                ldsm4t(rr, bl_base + off);
                blf[j * 2][0] = rr[0]; blf[j * 2][1] = rr[1];
                blf[j * 2 + 1][0] = rr[2]; blf[j * 2 + 1][1] = rr[3];
            }
            #pragma unroll
            for (int mf = 0; mf < 2; mf++)
                #pragma unroll
                for (int j = 0; j < 4; j++) {
                    int nf = h * 4 + j;
                    MMA_BF16(c[mf][nf], ah[mf], bhf[j][0], bhf[j][1]);
                    MMA_BF16(c[mf][nf], ah[mf], blf[j][0], blf[j][1]);
                    MMA_BF16(c[mf][nf], al[mf], bhf[j][0], bhf[j][1]);
                }
        }
    };

    // ---- main loop: 4-stage cp.async pipeline ----
    const int ntk = K / BK;
    issue(0); issue(1); issue(2);
    for (int kt = 0; kt < ntk; kt++) {
        asm volatile("cp.async.wait_group 2;" ::: "memory");
        __syncthreads();
        compute(kt & 3);
        if (kt + 3 < ntk) issue(kt + 3);
        else asm volatile("cp.async.commit_group;" ::: "memory");
    }

    // ---- epilogue ----
    const bool evenN = ((N & 1) == 0);
    #pragma unroll
    for (int mf = 0; mf < 2; mf++) {
        int r0 = m0 + wm * 32 + mf * 16 + lq;
        int r1 = r0 + 8;
        #pragma unroll
        for (int nf = 0; nf < 8; nf++) {
            int col = n0 + wn * 64 + nf * 8 + 2 * lr;
            size_t o0 = (size_t)r0 * N + col;
            size_t o1 = (size_t)r1 * N + col;
            float2 v0 = make_float2(c[mf][nf][0], c[mf][nf][1]);
            float2 v1 = make_float2(c[mf][nf][2], c[mf][nf][3]);
            if (col + 2 <= N) {
                if (EPI == 1) {
                    float2 x0 = *(const float2*)(X + o0);
                    float2 x1 = *(const float2*)(X + o1);
                    v0.x += x0.x; v0.y += x0.y; v1.x += x1.x; v1.y += x1.y;
                } else if (EPI == 2) {
                    float2 x0 = *(const float2*)(X + o0);
                    float2 x1 = *(const float2*)(X + o1);
                    v0.x *= x0.x / (1.0f + __expf(-x0.x));
                    v0.y *= x0.y / (1.0f + __expf(-x0.y));
                    v1.x *= x1.x / (1.0f + __expf(-x1.x));
                    v1.y *= x1.y / (1.0f + __expf(-x1.y));
                }
                if (OUTHL) {
                    uint32_t h0, l0, h1, l1;
                    split2(v0.x, v0.y, h0, l0);
                    split2(v1.x, v1.y, h1, l1);
                    *(uint32_t*)(Oh + o0) = h0;
                    *(uint32_t*)(Ol + o0) = l0;
                    *(uint32_t*)(Oh + o1) = h1;
                    *(uint32_t*)(Ol + o1) = l1;
                } else if (evenN) {
                    *(float2*)(C + o0) = v0;
                    *(float2*)(C + o1) = v1;
                } else {
                    // odd N (LM head): row base parity varies -> scalar stores
                    C[o0] = v0.x; C[o0 + 1] = v0.y;
                    C[o1] = v1.x; C[o1 + 1] = v1.y;
                }
            } else if (col < N) {
                float a0 = v0.x, a1 = v1.x;
                if (EPI == 1) { a0 += X[o0]; a1 += X[o1]; }
                else if (EPI == 2) {
                    float x0 = X[o0], x1 = X[o1];
                    a0 *= x0 / (1.0f + __expf(-x0));
                    a1 *= x1 / (1.0f + __expf(-x1));
                }
                C[o0] = a0; C[o1] = a1;
            }
        }
    }
}

// ---------------- split-KV flash attention (causal, fp32) ------------------
// grid (NB_*NH, 32): y encodes (qg, half); qg = 15 - (y>>1) (longest first),
// half = y&1 processes KV tiles {half, half+2, ...} of 0..qg.
// block 128: 64 q-rows, pair (lane, lane^1) splits dims.
// Writes UNNORMALIZED o + (m, l) partials to scratch.
__global__ __launch_bounds__(128)
void attn_part_kernel(const float* __restrict__ qkv,
                      float* __restrict__ po,
                      float* __restrict__ pm,
                      float* __restrict__ pl) {
    const int bh = blockIdx.x;
    const int b  = bh >> 4;
    const int hd = bh & 15;
    const int qg   = 15 - (blockIdx.y >> 1);   // longest blocks launch first
    const int half = blockIdx.y & 1;
    const int tid = threadIdx.x;          // 0..127
    const int row = tid >> 1;             // 0..63
    const int hdim = tid & 1;
    const int qrow = qg * 64 + row;
    const int doff = hdim * 4;

    const float* qptr = qkv + ((size_t)(b * NS + qrow) * (3 * ND)) + hd * NDH;
    float4 q[8];
    #pragma unroll
    for (int i = 0; i < 8; i++)
        q[i] = *(const float4*)(qptr + i * 8 + doff);

    float4 o[8];
    #pragma unroll
    for (int i = 0; i < 8; i++) o[i] = make_float4(0.f, 0.f, 0.f, 0.f);
    float m = -1e30f, l = 0.0f;

    __shared__ float ksm[64][64];
    __shared__ float vsm[64][64];

    const int ntiles = qg + 1;
    for (int kt = half; kt < ntiles; kt += 2) {
        const int kbase = kt * 64;
        #pragma unroll
        for (int i = 0; i < 8; i++) {
            int li = tid + i * 128;
            int r  = li >> 4;
            int c4 = (li & 15) * 4;
            const float* base = qkv + ((size_t)(b * NS + kbase + r) * (3 * ND))
                                + hd * NDH + c4;
            *(float4*)&ksm[r][c4] = *(const float4*)(base + ND);
            *(float4*)&vsm[r][c4] = *(const float4*)(base + 2 * ND);
        }
        __syncthreads();

        #pragma unroll 1
        for (int jt = 0; jt < 4; jt++) {
            float s[16];
            #pragma unroll
            for (int j = 0; j < 16; j++) {
                int jr = jt * 16 + j;
                float a = 0.0f;
                #pragma unroll
                for (int i = 0; i < 8; i++) {
                    float4 kv = *(const float4*)&ksm[jr][i * 8 + doff];
                    a += q[i].x * kv.x + q[i].y * kv.y
                       + q[i].z * kv.z + q[i].w * kv.w;
                }
                a += __shfl_xor_sync(0xFFFFFFFFu, a, 1);
                int key = kbase + jr;
                s[j] = (key <= qrow) ? a * 0.125f : -1e30f;
            }
            float tm = s[0];
            #pragma unroll
            for (int j = 1; j < 16; j++) tm = fmaxf(tm, s[j]);
            float mnew = fmaxf(m, tm);
            float corr = __expf(m - mnew);
            float psum = 0.0f;
            #pragma unroll
            for (int j = 0; j < 16; j++) {
                s[j] = __expf(s[j] - mnew);
                psum += s[j];
            }
            l = l * corr + psum;
            m = mnew;
            #pragma unroll
            for (int i = 0; i < 8; i++) {
                o[i].x *= corr; o[i].y *= corr; o[i].z *= corr; o[i].w *= corr;
            }
            #pragma unroll
            for (int j = 0; j < 16; j++) {
                float p = s[j];
                int jr = jt * 16 + j;
                #pragma unroll
                for (int i = 0; i < 8; i++) {
                    float4 vv = *(const float4*)&vsm[jr][i * 8 + doff];
                    o[i].x += p * vv.x; o[i].y += p * vv.y;
                    o[i].z += p * vv.z; o[i].w += p * vv.w;
                }
            }
        }
        __syncthreads();
    }

    // write partials (unnormalized o; m, l per row/head)
    const size_t tok = (size_t)(b * NS + qrow);
    if (hdim == 0) {
        pm[(size_t)half * (MTOK * NH) + tok * NH + hd] = m;
        pl[(size_t)half * (MTOK * NH) + tok * NH + hd] = l;
    }
    float* op = po + (size_t)half * (MTOK * ND) + tok * ND + hd * NDH;
    #pragma unroll
    for (int i = 0; i < 8; i++)
        *(float4*)(op + i * 8 + doff) = o[i];
}

// ---------------- attention merge: combine 2 halves -> bf16 hi/lo ----------
// grid (MTOK), block 256: thread t handles head t>>4, dims (t&15)*4..+3.
__global__ __launch_bounds__(256)
void attn_merge_kernel(const float* __restrict__ po,
                       const float* __restrict__ pm,
                       const float* __restrict__ pl,
                       uint16_t* __restrict__ yh, uint16_t* __restrict__ yl) {
    const int tok = blockIdx.x;
    const int t = threadIdx.x;
    const int hd = t >> 4;
    const int d4 = (t & 15) * 4;

    float m1 = pm[(size_t)tok * NH + hd];
    float l1 = pl[(size_t)tok * NH + hd];
    float m2 = pm[(size_t)(MTOK * NH) + (size_t)tok * NH + hd];
    float l2 = pl[(size_t)(MTOK * NH) + (size_t)tok * NH + hd];
    float M = fmaxf(m1, m2);
    float s1 = __expf(m1 - M);
    float s2 = __expf(m2 - M);
    float inv = 1.0f / (l1 * s1 + l2 * s2);

    size_t off = (size_t)tok * ND + hd * NDH + d4;
    float4 o1 = *(const float4*)(po + off);
    float4 o2 = *(const float4*)(po + (size_t)(MTOK * ND) + off);
    float4 r;
    r.x = (o1.x * s1 + o2.x * s2) * inv;
    r.y = (o1.y * s1 + o2.y * s2) * inv;
    r.z = (o1.z * s1 + o2.z * s2) * inv;
    r.w = (o1.w * s1 + o2.w * s2) * inv;
    uint2 hi, lo;
    split4(r, hi, lo);
    *(uint2*)(yh + off) = hi;
    *(uint2*)(yl + off) = lo;
}

// ---------------- launch ----------------
extern "C" void kernel_launch(void* const* d_in, const int* in_sizes, int n_in,
                              void* d_out, int out_size) {
    const int*   idx   = (const int*)  d_in[0];
    const float* wte   = (const float*)d_in[1];
    const float* wpe   = (const float*)d_in[2];
    const float* g1    = (const float*)d_in[3];
    const float* Wqkv  = (const float*)d_in[4];
    const float* Wproj = (const float*)d_in[5];
    const float* g2    = (const float*)d_in[6];
    const float* Wg    = (const float*)d_in[7];
    const float* Wu    = (const float*)d_in[8];
    const float* Wd    = (const float*)d_in[9];
    const float* gf    = (const float*)d_in[10];
    const float* Wlm   = (const float*)d_in[11];
    float* out = (float*)d_out;

    float *px, *pqkv, *pgate, *ppo, *ppm, *ppl;
    uint16_t *phh, *phl, *pyh, *pyl, *psh, *psl;
    uint16_t *wqh, *wql, *wph, *wpl, *wgh, *wgl, *wuh, *wul, *wdh, *wdl, *wlh, *wll;
    cudaGetSymbolAddress((void**)&px,    g_x);
    cudaGetSymbolAddress((void**)&pqkv,  g_qkv);
    cudaGetSymbolAddress((void**)&pgate, g_gate);
    cudaGetSymbolAddress((void**)&ppo,   g_po);
    cudaGetSymbolAddress((void**)&ppm,   g_pm);
    cudaGetSymbolAddress((void**)&ppl,   g_pl);
    cudaGetSymbolAddress((void**)&phh,   g_hh);
    cudaGetSymbolAddress((void**)&phl,   g_hl);
    cudaGetSymbolAddress((void**)&pyh,   g_yh);
    cudaGetSymbolAddress((void**)&pyl,   g_yl);
    cudaGetSymbolAddress((void**)&psh,   g_sh);
    cudaGetSymbolAddress((void**)&psl,   g_sl);
    cudaGetSymbolAddress((void**)&wqh,   g_wqkv_h);
    cudaGetSymbolAddress((void**)&wql,   g_wqkv_l);
    cudaGetSymbolAddress((void**)&wph,   g_wproj_h);
    cudaGetSymbolAddress((void**)&wpl,   g_wproj_l);
    cudaGetSymbolAddress((void**)&wgh,   g_wg_h);
    cudaGetSymbolAddress((void**)&wgl,   g_wg_l);
    cudaGetSymbolAddress((void**)&wuh,   g_wu_h);
    cudaGetSymbolAddress((void**)&wul,   g_wu_l);
    cudaGetSymbolAddress((void**)&wdh,   g_wd_h);
    cudaGetSymbolAddress((void**)&wdl,   g_wd_l);
    cudaGetSymbolAddress((void**)&wlh,   g_wlm_h);
    cudaGetSymbolAddress((void**)&wll,   g_wlm_l);

    cudaFuncSetAttribute(gemm_bf<0, false>,
        cudaFuncAttributeMaxDynamicSharedMemorySize, SMEM_BYTES);
    cudaFuncSetAttribute(gemm_bf<1, false>,
        cudaFuncAttributeMaxDynamicSharedMemorySize, SMEM_BYTES);
    cudaFuncSetAttribute(gemm_bf<2, true>,
        cudaFuncAttributeMaxDynamicSharedMemorySize, SMEM_BYTES);

    // ---- weight split (runs each call) ----
    {
        int n4;
        n4 = NL * ND * 3 * ND / 4;
        wsplit_kernel<<<(n4 + 255) / 256, 256>>>(Wqkv, wqh, wql, n4);
        n4 = NL * ND * ND / 4;
        wsplit_kernel<<<(n4 + 255) / 256, 256>>>(Wproj, wph, wpl, n4);
        n4 = NL * ND * NHID / 4;
        wsplit_kernel<<<(n4 + 255) / 256, 256>>>(Wg, wgh, wgl, n4);
        wsplit_kernel<<<(n4 + 255) / 256, 256>>>(Wu, wuh, wul, n4);
        n4 = NL * NHID * ND / 4;
        wsplit_kernel<<<(n4 + 255) / 256, 256>>>(Wd, wdh, wdl, n4);
        wsplit_pad_kernel<<<dim3((NVP + 255) / 256, ND), 256>>>(Wlm, wlh, wll);
    }

    embed_kernel<<<MTOK, 256>>>(idx, wte, wpe, px);

    for (int l = 0; l < NL; l++) {
        rmsnorm_hl_kernel<<<MTOK, 256>>>(px, g1 + (size_t)l * ND, phh, phl);
        gemm_bf<0, false><<<dim3(3 * ND / BN, MTOK / BM), 256, SMEM_BYTES>>>(
            phh, phl, wqh + (size_t)l * ND * 3 * ND, wql + (size_t)l * ND * 3 * ND,
            nullptr, pqkv, nullptr, nullptr, MTOK, 3 * ND, 3 * ND, ND);
        attn_part_kernel<<<dim3(NB_ * NH, 32), 128>>>(pqkv, ppo, ppm, ppl);
        attn_merge_kernel<<<MTOK, 256>>>(ppo, ppm, ppl, pyh, pyl);
        gemm_bf<1, false><<<dim3(ND / BN, MTOK / BM), 256, SMEM_BYTES>>>(
            pyh, pyl, wph + (size_t)l * ND * ND, wpl + (size_t)l * ND * ND,
            px, px, nullptr, nullptr, MTOK, ND, ND, ND);
        rmsnorm_hl_kernel<<<MTOK, 256>>>(px, g2 + (size_t)l * ND, phh, phl);
        gemm_bf<0, false><<<dim3(NHID / BN, MTOK / BM), 256, SMEM_BYTES>>>(
            phh, phl, wgh + (size_t)l * ND * NHID, wgl + (size_t)l * ND * NHID,
            nullptr, pgate, nullptr, nullptr, MTOK, NHID, NHID, ND);
        gemm_bf<2, true><<<dim3(NHID / BN, MTOK / BM), 256, SMEM_BYTES>>>(
            phh, phl, wuh + (size_t)l * ND * NHID, wul + (size_t)l * ND * NHID,
            pgate, nullptr, psh, psl, MTOK, NHID, NHID, ND);
        gemm_bf<1, false><<<dim3(ND / BN, MTOK / BM), 256, SMEM_BYTES>>>(
            psh, psl, wdh + (size_t)l * NHID * ND, wdl + (size_t)l * NHID * ND,
            px, px, nullptr, nullptr, MTOK, ND, ND, NHID);
    }

    rmsnorm_hl_kernel<<<MTOK, 256>>>(px, gf, phh, phl);
    gemm_bf<0, false><<<dim3(NVP / BN, MTOK / BM), 256, SMEM_BYTES>>>(
        phh, phl, wlh, wll, nullptr, out, nullptr, nullptr, MTOK, NV, NVP, ND);
}

// round 14
// speedup vs baseline: 1.3408x; 1.0908x over previous
#include <cuda_runtime.h>
#include <cuda_fp16.h>
#include <math.h>
#include <stdint.h>

// Problem constants
#define NB_  2
#define NS   1024
#define ND   1024
#define NH   16
#define NDH  64
#define NL   12
#define NHID 2816
#define NV   50257
#define NVP  50304   // padded LM-head N (128*393)
#define MTOK 2048    // NB_*NS

// GEMM tiling: 128x128 block, BK=16, 8 warps (4m x 2n), warp tile 32x64
#define BM 128
#define BN 128
#define BK 16
#define STAGE_BYTES 16384
#define NSTAGE 4
#define SMEM_BYTES (NSTAGE * STAGE_BYTES)

// ---------------- activation scratch ----------------
__device__ float    g_x[MTOK * ND];            // residual (fp32)
__device__ uint16_t g_hh[MTOK * ND];           // rmsnorm out hi (bf16) / fp16 (final)
__device__ uint16_t g_hl[MTOK * ND];           // rmsnorm out lo
__device__ float    g_qkv[MTOK * 3 * ND];      // qkv (fp32)
__device__ uint16_t g_yh[MTOK * ND];           // attn out hi
__device__ uint16_t g_yl[MTOK * ND];           // attn out lo
__device__ float    g_gate[MTOK * NHID];       // gate pre-act (fp32)
__device__ uint16_t g_sh[MTOK * NHID];         // swiglu out hi
__device__ uint16_t g_sl[MTOK * NHID];         // swiglu out lo
// split-KV attention partials (2 halves)
__device__ float    g_po[2 * MTOK * ND];       // unnormalized o
__device__ float    g_pm[2 * MTOK * NH];       // running max
__device__ float    g_pl[2 * MTOK * NH];       // running sum

// ---------------- weight scratch ----------------
__device__ uint16_t g_wqkv_h[NL * ND * 3 * ND];
__device__ uint16_t g_wqkv_l[NL * ND * 3 * ND];
__device__ uint16_t g_wproj_h[NL * ND * ND];
__device__ uint16_t g_wproj_l[NL * ND * ND];
__device__ uint16_t g_wg_h[NL * ND * NHID];
__device__ uint16_t g_wg_l[NL * ND * NHID];
__device__ uint16_t g_wu_h[NL * ND * NHID];
__device__ uint16_t g_wu_l[NL * ND * NHID];
__device__ uint16_t g_wd_h[NL * NHID * ND];
__device__ uint16_t g_wd_l[NL * NHID * ND];
__device__ uint16_t g_wlm_h[ND * NVP];         // fp16 (single precision pass)

// ---------------- helpers ----------------
// A tile smem: 128 rows x 16 bf16 (32B/row), chunk-swizzled for LDSM
__device__ __forceinline__ uint32_t a_off(int m, int k) {
    uint32_t chunk = ((uint32_t)(k >> 3) ^ ((uint32_t)(m >> 2) & 1u)) & 1u;
    return (uint32_t)m * 32u + chunk * 16u + (uint32_t)(k & 7) * 2u;
}
// B tile smem: 16 rows x 128 bf16 (256B/row), chunk-swizzled for LDSM.trans
__device__ __forceinline__ uint32_t b_off(int k, int n) {
    uint32_t nb = (uint32_t)(n >> 3);
    uint32_t chunk = (nb & 8u) | ((nb ^ ((uint32_t)k & 7u)) & 7u);
    return (uint32_t)k * 256u + chunk * 16u + (uint32_t)(n & 7) * 2u;
}

__device__ __forceinline__ void ldsm4(uint32_t* r, uint32_t addr) {
    asm volatile("ldmatrix.sync.aligned.m8n8.x4.shared.b16 {%0,%1,%2,%3}, [%4];"
        : "=r"(r[0]), "=r"(r[1]), "=r"(r[2]), "=r"(r[3]) : "r"(addr));
}
__device__ __forceinline__ void ldsm4t(uint32_t* r, uint32_t addr) {
    asm volatile("ldmatrix.sync.aligned.m8n8.x4.trans.shared.b16 {%0,%1,%2,%3}, [%4];"
        : "=r"(r[0]), "=r"(r[1]), "=r"(r[2]), "=r"(r[3]) : "r"(addr));
}
#define MMA_BF16(acc, a, b0, b1)                                              \
    asm volatile(                                                              \
        "mma.sync.aligned.m16n8k16.row.col.f32.bf16.bf16.f32 "                 \
        "{%0,%1,%2,%3}, {%4,%5,%6,%7}, {%8,%9}, {%0,%1,%2,%3};"                \
        : "+f"(acc[0]), "+f"(acc[1]), "+f"(acc[2]), "+f"(acc[3])               \
        : "r"(a[0]), "r"(a[1]), "r"(a[2]), "r"(a[3]), "r"(b0), "r"(b1))

#define MMA_F16(acc, a, b0, b1)                                               \
    asm volatile(                                                              \
        "mma.sync.aligned.m16n8k16.row.col.f32.f16.f16.f32 "                   \
        "{%0,%1,%2,%3}, {%4,%5,%6,%7}, {%8,%9}, {%0,%1,%2,%3};"                \
        : "+f"(acc[0]), "+f"(acc[1]), "+f"(acc[2]), "+f"(acc[3])               \
        : "r"(a[0]), "r"(a[1]), "r"(a[2]), "r"(a[3]), "r"(b0), "r"(b1))

#define CPASYNC16(dst, src)                                                    \
    asm volatile("cp.async.cg.shared.global [%0], [%1], 16;"                   \
                 :: "r"(dst), "l"(src))

// split float4 into bf16x4 hi (rn) + lo (rn of residual)
__device__ __forceinline__ void split4(float4 v, uint2& hi, uint2& lo) {
    uint32_t h0, h1, l0, l1;
    asm("cvt.rn.bf16x2.f32 %0, %1, %2;" : "=r"(h0) : "f"(v.y), "f"(v.x));
    asm("cvt.rn.bf16x2.f32 %0, %1, %2;" : "=r"(h1) : "f"(v.w), "f"(v.z));
    float hx = __uint_as_float(h0 << 16);
    float hy = __uint_as_float(h0 & 0xffff0000u);
    float hz = __uint_as_float(h1 << 16);
    float hw = __uint_as_float(h1 & 0xffff0000u);
    float lx = v.x - hx, ly = v.y - hy, lz = v.z - hz, lw = v.w - hw;
    asm("cvt.rn.bf16x2.f32 %0, %1, %2;" : "=r"(l0) : "f"(ly), "f"(lx));
    asm("cvt.rn.bf16x2.f32 %0, %1, %2;" : "=r"(l1) : "f"(lw), "f"(lz));
    hi.x = h0; hi.y = h1; lo.x = l0; lo.y = l1;
}
// split pair (a=elem0, b=elem1) into hi/lo bf16x2 words
__device__ __forceinline__ void split2(float a, float b, uint32_t& h, uint32_t& l) {
    asm("cvt.rn.bf16x2.f32 %0, %1, %2;" : "=r"(h) : "f"(b), "f"(a));
    float ha = __uint_as_float(h << 16);
    float hb = __uint_as_float(h & 0xffff0000u);
    asm("cvt.rn.bf16x2.f32 %0, %1, %2;" : "=r"(l) : "f"(b - hb), "f"(a - ha));
}

// ---------------- weight split kernels ----------------
__global__ void wsplit_kernel(const float* __restrict__ w,
                              uint16_t* __restrict__ wh,
                              uint16_t* __restrict__ wl, int n4) {
    int i = blockIdx.x * 256 + threadIdx.x;
    if (i < n4) {
        float4 v = ((const float4*)w)[i];
        uint2 hi, lo;
        split4(v, hi, lo);
        ((uint2*)wh)[i] = hi;
        ((uint2*)wl)[i] = lo;
    }
}
// LM head: pad [1024,50257] -> [1024,50304] with zeros, convert to fp16
__global__ void wconv_pad_f16_kernel(const float* __restrict__ w,
                                     uint16_t* __restrict__ wh) {
    int c = blockIdx.x * 256 + threadIdx.x;
    int r = blockIdx.y;
    if (c < NVP) {
        float x = (c < NV) ? w[(size_t)r * NV + c] : 0.0f;
        wh[(size_t)r * NVP + c] = __half_as_ushort(__float2half_rn(x));
    }
}

// ---------------- embedding ----------------
__global__ void embed_kernel(const int* __restrict__ idx,
                             const float* __restrict__ wte,
                             const float* __restrict__ wpe,
                             float* __restrict__ x) {
    int row = blockIdx.x;
    int t = threadIdx.x;
    int tok = idx[row];
    int spos = row & (NS - 1);
    float4 a = ((const float4*)(wte + (size_t)tok * ND))[t];
    float4 b = ((const float4*)(wpe + (size_t)spos * ND))[t];
    float4 o;
    o.x = a.x + b.x; o.y = a.y + b.y; o.z = a.z + b.z; o.w = a.w + b.w;
    ((float4*)(x + (size_t)row * ND))[t] = o;
}

// ---------------- rmsnorm -> bf16 hi/lo ----------------
__global__ void rmsnorm_hl_kernel(const float* __restrict__ in,
                                  const float* __restrict__ gamma,
                                  uint16_t* __restrict__ oh,
                                  uint16_t* __restrict__ ol) {
    int row = blockIdx.x;
    int t = threadIdx.x;
    float4 v = ((const float4*)(in + (size_t)row * ND))[t];
    float ss = v.x * v.x + v.y * v.y + v.z * v.z + v.w * v.w;
    #pragma unroll
    for (int off = 16; off; off >>= 1)
        ss += __shfl_xor_sync(0xFFFFFFFFu, ss, off);
    __shared__ float red[8];
    if ((t & 31) == 0) red[t >> 5] = ss;
    __syncthreads();
    float tot = red[0] + red[1] + red[2] + red[3] +
                red[4] + red[5] + red[6] + red[7];
    float r = rsqrtf(tot * (1.0f / (float)ND) + 1e-12f);
    float4 g = ((const float4*)gamma)[t];
    float4 o;
    o.x = v.x * r * g.x; o.y = v.y * r * g.y;
    o.z = v.z * r * g.z; o.w = v.w * r * g.w;
    uint2 hi, lo;
    split4(o, hi, lo);
    ((uint2*)oh)[row * 256 + t] = hi;
    ((uint2*)ol)[row * 256 + t] = lo;
}

// ---------------- rmsnorm -> fp16 (final norm, feeds fp16 LM head) --------
__global__ void rmsnorm_f16_kernel(const float* __restrict__ in,
                                   const float* __restrict__ gamma,
                                   uint16_t* __restrict__ oh) {
    int row = blockIdx.x;
    int t = threadIdx.x;
    float4 v = ((const float4*)(in + (size_t)row * ND))[t];
    float ss = v.x * v.x + v.y * v.y + v.z * v.z + v.w * v.w;
    #pragma unroll
    for (int off = 16; off; off >>= 1)
        ss += __shfl_xor_sync(0xFFFFFFFFu, ss, off);
    __shared__ float red[8];
    if ((t & 31) == 0) red[t >> 5] = ss;
    __syncthreads();
    float tot = red[0] + red[1] + red[2] + red[3] +
                red[4] + red[5] + red[6] + red[7];
    float r = rsqrtf(tot * (1.0f / (float)ND) + 1e-12f);
    float4 g = ((const float4*)gamma)[t];
    __half2 p0 = __floats2half2_rn(v.x * r * g.x, v.y * r * g.y);
    __half2 p1 = __floats2half2_rn(v.z * r * g.z, v.w * r * g.w);
    uint2 o;
    o.x = *(uint32_t*)&p0;
    o.y = *(uint32_t*)&p1;
    ((uint2*)oh)[row * 256 + t] = o;
}

// ---------------- bf16 tensor-core GEMM, cp.async 4-stage ------------------
// C[M,N] = epi(A[M,K] @ B[K,N]) with A,B given as bf16 hi/lo pairs.
// EPI 0: C = acc (fp32) ; EPI 1: C = X + acc (fp32) ; EPI 2: silu(X)*acc
// OUTHL: write result as bf16 hi/lo to Oh/Ol instead of fp32 C.
template<int EPI, bool OUTHL>
__global__ __launch_bounds__(256, 2)
void gemm_bf(const uint16_t* __restrict__ Ah, const uint16_t* __restrict__ Al,
             const uint16_t* __restrict__ Bh, const uint16_t* __restrict__ Bl,
             const float* __restrict__ X, float* __restrict__ C,
             uint16_t* __restrict__ Oh, uint16_t* __restrict__ Ol,
             int M, int N, int NBs, int K) {
    extern __shared__ __align__(16) char sm[];
    const uint32_t sb = (uint32_t)__cvta_generic_to_shared(sm);

    const int tid  = threadIdx.x;
    const int lane = tid & 31;
    const int warp = tid >> 5;
    const int wm = warp & 3;
    const int wn = warp >> 2;
    const int lq = lane >> 2;
    const int lr = lane & 3;
    const int m0 = blockIdx.y * BM;
    const int n0 = blockIdx.x * BN;

    float c[2][8][4];
    #pragma unroll
    for (int i = 0; i < 2; i++)
        #pragma unroll
        for (int j = 0; j < 8; j++)
            #pragma unroll
            for (int k = 0; k < 4; k++) c[i][j][k] = 0.0f;

    const int am = tid >> 1;
    const int ak = (tid & 1) * 8;
    const int bk = tid >> 4;
    const int bn = (tid & 15) * 8;
    const uint32_t a_dst = a_off(am, ak);
    const uint32_t b_dst = b_off(bk, bn);

    auto issue = [&](int kt) {
        const int kbase = kt * BK;
        const uint32_t stg = sb + (uint32_t)(kt & 3) * (uint32_t)STAGE_BYTES;
        const uint16_t* sa = Ah + (size_t)(m0 + am) * K + kbase + ak;
        const uint16_t* sa2 = Al + (size_t)(m0 + am) * K + kbase + ak;
        CPASYNC16(stg + a_dst, sa);
        CPASYNC16(stg + 4096u + a_dst, sa2);
        const uint16_t* sbh = Bh + (size_t)(kbase + bk) * NBs + n0 + bn;
        const uint16_t* sbl = Bl + (size_t)(kbase + bk) * NBs + n0 + bn;
        CPASYNC16(stg + 8192u + b_dst, sbh);
        CPASYNC16(stg + 12288u + b_dst, sbl);
        asm volatile("cp.async.commit_group;" ::: "memory");
    };

    const int lid8 = lane >> 3;
    const int lrow = lane & 7;

    auto compute = [&](int buf) {
        const uint32_t ah_base = sb + (uint32_t)buf * (uint32_t)STAGE_BYTES;
        const uint32_t al_base = ah_base + 4096u;
        const uint32_t bh_base = ah_base + 8192u;
        const uint32_t bl_base = ah_base + 12288u;

        uint32_t ah[2][4], al[2][4];
        {
            int m = ((lid8 & 1) << 3) + lrow;
            int k = (lid8 >> 1) << 3;
            #pragma unroll
            for (int mf = 0; mf < 2; mf++) {
                uint32_t off = a_off(wm * 32 + mf * 16 + m, k);
                ldsm4(ah[mf], ah_base + off);
                ldsm4(al[mf], al_base + off);
            }
        }
        #pragma unroll
        for (int h = 0; h < 2; h++) {
            uint32_t bhf[4][2], blf[4][2];
            #pragma unroll
            for (int j = 0; j < 2; j++) {
                int k  = ((lid8 & 1) << 3) + lrow;
                int nb = wn * 8 + h * 4 + j * 2 + (lid8 >> 1);
                uint32_t off = b_off(k, nb << 3);
                uint32_t rr[4];
                ldsm4t(rr, bh_base + off);
                bhf[j * 2][0] = rr[0]; bhf[j * 2][1] = rr[1];
                bhf[j * 2 + 1][0] = rr[2]; bhf[j * 2 + 1][1] = rr[3];
                ldsm4t(rr, bl_base + off);
                blf[j * 2][0] = rr[0]; blf[j * 2][1] = rr[1];
                blf[j * 2 + 1][0] = rr[2]; blf[j * 2 + 1][1] = rr[3];
            }
            #pragma unroll
            for (int mf = 0; mf < 2; mf++)
                #pragma unroll
                for (int j = 0; j < 4; j++) {
                    int nf = h * 4 + j;
                    MMA_BF16(c[mf][nf], ah[mf], bhf[j][0], bhf[j][1]);
                    MMA_BF16(c[mf][nf], ah[mf], blf[j][0], blf[j][1]);
                    MMA_BF16(c[mf][nf], al[mf], bhf[j][0], bhf[j][1]);
                }
        }
    };

    const int ntk = K / BK;
    issue(0); issue(1); issue(2);
    for (int kt = 0; kt < ntk; kt++) {
        asm volatile("cp.async.wait_group 2;" ::: "memory");
        __syncthreads();
        compute(kt & 3);
        if (kt + 3 < ntk) issue(kt + 3);
        else asm volatile("cp.async.commit_group;" ::: "memory");
    }

    #pragma unroll
    for (int mf = 0; mf < 2; mf++) {
        int r0 = m0 + wm * 32 + mf * 16 + lq;
        int r1 = r0 + 8;
        #pragma unroll
        for (int nf = 0; nf < 8; nf++) {
            int col = n0 + wn * 64 + nf * 8 + 2 * lr;
            size_t o0 = (size_t)r0 * N + col;
            size_t o1 = (size_t)r1 * N + col;
            float2 v0 = make_float2(c[mf][nf][0], c[mf][nf][1]);
            float2 v1 = make_float2(c[mf][nf][2], c[mf][nf][3]);
            if (EPI == 1) {
                float2 x0 = *(const float2*)(X + o0);
                float2 x1 = *(const float2*)(X + o1);
                v0.x += x0.x; v0.y += x0.y; v1.x += x1.x; v1.y += x1.y;
            } else if (EPI == 2) {
                float2 x0 = *(const float2*)(X + o0);
                float2 x1 = *(const float2*)(X + o1);
                v0.x *= x0.x / (1.0f + __expf(-x0.x));
                v0.y *= x0.y / (1.0f + __expf(-x0.y));
                v1.x *= x1.x / (1.0f + __expf(-x1.x));
                v1.y *= x1.y / (1.0f + __expf(-x1.y));
            }
            if (OUTHL) {
                uint32_t h0, l0, h1, l1;
                split2(v0.x, v0.y, h0, l0);
                split2(v1.x, v1.y, h1, l1);
                *(uint32_t*)(Oh + o0) = h0;
                *(uint32_t*)(Ol + o0) = l0;
                *(uint32_t*)(Oh + o1) = h1;
                *(uint32_t*)(Ol + o1) = l1;
            } else {
                *(float2*)(C + o0) = v0;
                *(float2*)(C + o1) = v1;
            }
        }
    }
}

// ---------------- fp16 single-pass GEMM (LM head), cp.async 4-stage --------
// C[M,N] = A[M,K] @ B[K,N], A/B fp16. N may be odd (scalar store path).
#define F16_STAGE 8192
__global__ __launch_bounds__(256, 2)
void gemm_f16(const uint16_t* __restrict__ A, const uint16_t* __restrict__ B,
              float* __restrict__ C, int M, int N, int NBs, int K) {
    __shared__ __align__(16) char sm[NSTAGE * F16_STAGE];
    const uint32_t sb = (uint32_t)__cvta_generic_to_shared(sm);

    const int tid  = threadIdx.x;
    const int lane = tid & 31;
    const int warp = tid >> 5;
    const int wm = warp & 3;
    const int wn = warp >> 2;
    const int lq = lane >> 2;
    const int lr = lane & 3;
    const int m0 = blockIdx.y * BM;
    const int n0 = blockIdx.x * BN;

    float c[2][8][4];
    #pragma unroll
    for (int i = 0; i < 2; i++)
        #pragma unroll
        for (int j = 0; j < 8; j++)
            #pragma unroll
            for (int k = 0; k < 4; k++) c[i][j][k] = 0.0f;

    const int am = tid >> 1;
    const int ak = (tid & 1) * 8;
    const int bk = tid >> 4;
    const int bn = (tid & 15) * 8;
    const uint32_t a_dst = a_off(am, ak);
    const uint32_t b_dst = b_off(bk, bn);

    auto issue = [&](int kt) {
        const int kbase = kt * BK;
        const uint32_t stg = sb + (uint32_t)(kt & 3) * (uint32_t)F16_STAGE;
        CPASYNC16(stg + a_dst, A + (size_t)(m0 + am) * K + kbase + ak);
        CPASYNC16(stg + 4096u + b_dst, B + (size_t)(kbase + bk) * NBs + n0 + bn);
        asm volatile("cp.async.commit_group;" ::: "memory");
    };

    const int lid8 = lane >> 3;
    const int lrow = lane & 7;

    auto compute = [&](int buf) {
        const uint32_t a_base = sb + (uint32_t)buf * (uint32_t)F16_STAGE;
        const uint32_t b_base = a_base + 4096u;

        uint32_t af[2][4];
        {
            int m = ((lid8 & 1) << 3) + lrow;
            int k = (lid8 >> 1) << 3;
            #pragma unroll
            for (int mf = 0; mf < 2; mf++)
                ldsm4(af[mf], a_base + a_off(wm * 32 + mf * 16 + m, k));
        }
        #pragma unroll
        for (int h = 0; h < 2; h++) {
            uint32_t bf[4][2];
            #pragma unroll
            for (int j = 0; j < 2; j++) {
                int k  = ((lid8 & 1) << 3) + lrow;
                int nb = wn * 8 + h * 4 + j * 2 + (lid8 >> 1);
                uint32_t rr[4];
                ldsm4t(rr, b_base + b_off(k, nb << 3));
                bf[j * 2][0] = rr[0]; bf[j * 2][1] = rr[1];
                bf[j * 2 + 1][0] = rr[2]; bf[j * 2 + 1][1] = rr[3];
            }
            #pragma unroll
            for (int mf = 0; mf < 2; mf++)
                #pragma unroll
                for (int j = 0; j < 4; j++)
                    MMA_F16(c[mf][h * 4 + j], af[mf], bf[j][0], bf[j][1]);
        }
    };

    const int ntk = K / BK;
    issue(0); issue(1); issue(2);
    for (int kt = 0; kt < ntk; kt++) {
        asm volatile("cp.async.wait_group 2;" ::: "memory");
        __syncthreads();
        compute(kt & 3);
        if (kt + 3 < ntk) issue(kt + 3);
        else asm volatile("cp.async.commit_group;" ::: "memory");
    }

    const bool evenN = ((N & 1) == 0);
    #pragma unroll
    for (int mf = 0; mf < 2; mf++) {
        int r0 = m0 + wm * 32 + mf * 16 + lq;
        int r1 = r0 + 8;
        #pragma unroll
        for (int nf = 0; nf < 8; nf++) {
            int col = n0 + wn * 64 + nf * 8 + 2 * lr;
            size_t o0 = (size_t)r0 * N + col;
            size_t o1 = (size_t)r1 * N + col;
            if (col + 2 <= N) {
                if (evenN) {
                    *(float2*)(C + o0) = make_float2(c[mf][nf][0], c[mf][nf][1]);
                    *(float2*)(C + o1) = make_float2(c[mf][nf][2], c[mf][nf][3]);
                } else {
                    C[o0] = c[mf][nf][0]; C[o0 + 1] = c[mf][nf][1];
                    C[o1] = c[mf][nf][2]; C[o1 + 1] = c[mf][nf][3];
                }
            } else if (col < N) {
                C[o0] = c[mf][nf][0];
                C[o1] = c[mf][nf][2];
            }
        }
    }
}

// ---------------- split-KV flash attention (causal, fp32) ------------------
__global__ __launch_bounds__(128)
void attn_part_kernel(const float* __restrict__ qkv,
                      float* __restrict__ po,
                      float* __restrict__ pm,
                      float* __restrict__ pl) {
    const int bh = blockIdx.x;
    const int b  = bh >> 4;
    const int hd = bh & 15;
    const int qg   = 15 - (blockIdx.y >> 1);
    const int half = blockIdx.y & 1;
    const int tid = threadIdx.x;
    const int row = tid >> 1;
    const int hdim = tid & 1;
    const int qrow = qg * 64 + row;
    const int doff = hdim * 4;

    const float* qptr = qkv + ((size_t)(b * NS + qrow) * (3 * ND)) + hd * NDH;
    float4 q[8];
    #pragma unroll
    for (int i = 0; i < 8; i++)
        q[i] = *(const float4*)(qptr + i * 8 + doff);

    float4 o[8];
    #pragma unroll
    for (int i = 0; i < 8; i++) o[i] = make_float4(0.f, 0.f, 0.f, 0.f);
    float m = -1e30f, l = 0.0f;

    __shared__ float ksm[64][64];
    __shared__ float vsm[64][64];

    const int ntiles = qg + 1;
    for (int kt = half; kt < ntiles; kt += 2) {
        const int kbase = kt * 64;
        #pragma unroll
        for (int i = 0; i < 8; i++) {
            int li = tid + i * 128;
            int r  = li >> 4;
            int c4 = (li & 15) * 4;
            const float* base = qkv + ((size_t)(b * NS + kbase + r) * (3 * ND))
                                + hd * NDH + c4;
            *(float4*)&ksm[r][c4] = *(const float4*)(base + ND);
            *(float4*)&vsm[r][c4] = *(const float4*)(base + 2 * ND);
        }
        __syncthreads();

        #pragma unroll 1
        for (int jt = 0; jt < 4; jt++) {
            float s[16];
            #pragma unroll
            for (int j = 0; j < 16; j++) {
                int jr = jt * 16 + j;
                float a = 0.0f;
                #pragma unroll
                for (int i = 0; i < 8; i++) {
                    float4 kv = *(const float4*)&ksm[jr][i * 8 + doff];
                    a += q[i].x * kv.x + q[i].y * kv.y
                       + q[i].z * kv.z + q[i].w * kv.w;
                }
                a += __shfl_xor_sync(0xFFFFFFFFu, a, 1);
                int key = kbase + jr;
                s[j] = (key <= qrow) ? a * 0.125f : -1e30f;
            }
            float tm = s[0];
            #pragma unroll
            for (int j = 1; j < 16; j++) tm = fmaxf(tm, s[j]);
            float mnew = fmaxf(m, tm);
            float corr = __expf(m - mnew);
            float psum = 0.0f;
            #pragma unroll
            for (int j = 0; j < 16; j++) {
                s[j] = __expf(s[j] - mnew);
                psum += s[j];
            }
            l = l * corr + psum;
            m = mnew;
            #pragma unroll
            for (int i = 0; i < 8; i++) {
                o[i].x *= corr; o[i].y *= corr; o[i].z *= corr; o[i].w *= corr;
            }
            #pragma unroll
            for (int j = 0; j < 16; j++) {
                float p = s[j];
                int jr = jt * 16 + j;
                #pragma unroll
                for (int i = 0; i < 8; i++) {
                    float4 vv = *(const float4*)&vsm[jr][i * 8 + doff];
                    o[i].x += p * vv.x; o[i].y += p * vv.y;
                    o[i].z += p * vv.z; o[i].w += p * vv.w;
                }
            }
        }
        __syncthreads();
    }

    const size_t tok = (size_t)(b * NS + qrow);
    if (hdim == 0) {
        pm[(size_t)half * (MTOK * NH) + tok * NH + hd] = m;
        pl[(size_t)half * (MTOK * NH) + tok * NH + hd] = l;
    }
    float* op = po + (size_t)half * (MTOK * ND) + tok * ND + hd * NDH;
    #pragma unroll
    for (int i = 0; i < 8; i++)
        *(float4*)(op + i * 8 + doff) = o[i];
}

// ---------------- attention merge: combine 2 halves -> bf16 hi/lo ----------
__global__ __launch_bounds__(256)
void attn_merge_kernel(const float* __restrict__ po,
                       const float* __restrict__ pm,
                       const float* __restrict__ pl,
                       uint16_t* __restrict__ yh, uint16_t* __restrict__ yl) {
    const int tok = blockIdx.x;
    const int t = threadIdx.x;
    const int hd = t >> 4;
    const int d4 = (t & 15) * 4;

    float m1 = pm[(size_t)tok * NH + hd];
    float l1 = pl[(size_t)tok * NH + hd];
    float m2 = pm[(size_t)(MTOK * NH) + (size_t)tok * NH + hd];
    float l2 = pl[(size_t)(MTOK * NH) + (size_t)tok * NH + hd];
    float M = fmaxf(m1, m2);
    float s1 = __expf(m1 - M);
    float s2 = __expf(m2 - M);
    float inv = 1.0f / (l1 * s1 + l2 * s2);

    size_t off = (size_t)tok * ND + hd * NDH + d4;
    float4 o1 = *(const float4*)(po + off);
    float4 o2 = *(const float4*)(po + (size_t)(MTOK * ND) + off);
    float4 r;
    r.x = (o1.x * s1 + o2.x * s2) * inv;
    r.y = (o1.y * s1 + o2.y * s2) * inv;
    r.z = (o1.z * s1 + o2.z * s2) * inv;
    r.w = (o1.w * s1 + o2.w * s2) * inv;
    uint2 hi, lo;
    split4(r, hi, lo);
    *(uint2*)(yh + off) = hi;
    *(uint2*)(yl + off) = lo;
}

// ---------------- launch ----------------
extern "C" void kernel_launch(void* const* d_in, const int* in_sizes, int n_in,
                              void* d_out, int out_size) {
    const int*   idx   = (const int*)  d_in[0];
    const float* wte   = (const float*)d_in[1];
    const float* wpe   = (const float*)d_in[2];
    const float* g1    = (const float*)d_in[3];
    const float* Wqkv  = (const float*)d_in[4];
    const float* Wproj = (const float*)d_in[5];
    const float* g2    = (const float*)d_in[6];
    const float* Wg    = (const float*)d_in[7];
    const float* Wu    = (const float*)d_in[8];
    const float* Wd    = (const float*)d_in[9];
    const float* gf    = (const float*)d_in[10];
    const float* Wlm   = (const float*)d_in[11];
    float* out = (float*)d_out;

    float *px, *pqkv, *pgate, *ppo, *ppm, *ppl;
    uint16_t *phh, *phl, *pyh, *pyl, *psh, *psl;
    uint16_t *wqh, *wql, *wph, *wpl, *wgh, *wgl, *wuh, *wul, *wdh, *wdl, *wlh;
    cudaGetSymbolAddress((void**)&px,    g_x);
    cudaGetSymbolAddress((void**)&pqkv,  g_qkv);
    cudaGetSymbolAddress((void**)&pgate, g_gate);
    cudaGetSymbolAddress((void**)&ppo,   g_po);
    cudaGetSymbolAddress((void**)&ppm,   g_pm);
    cudaGetSymbolAddress((void**)&ppl,   g_pl);
    cudaGetSymbolAddress((void**)&phh,   g_hh);
    cudaGetSymbolAddress((void**)&phl,   g_hl);
    cudaGetSymbolAddress((void**)&pyh,   g_yh);
    cudaGetSymbolAddress((void**)&pyl,   g_yl);
    cudaGetSymbolAddress((void**)&psh,   g_sh);
    cudaGetSymbolAddress((void**)&psl,   g_sl);
    cudaGetSymbolAddress((void**)&wqh,   g_wqkv_h);
    cudaGetSymbolAddress((void**)&wql,   g_wqkv_l);
    cudaGetSymbolAddress((void**)&wph,   g_wproj_h);
    cudaGetSymbolAddress((void**)&wpl,   g_wproj_l);
    cudaGetSymbolAddress((void**)&wgh,   g_wg_h);
    cudaGetSymbolAddress((void**)&wgl,   g_wg_l);
    cudaGetSymbolAddress((void**)&wuh,   g_wu_h);
    cudaGetSymbolAddress((void**)&wul,   g_wu_l);
    cudaGetSymbolAddress((void**)&wdh,   g_wd_h);
    cudaGetSymbolAddress((void**)&wdl,   g_wd_l);
    cudaGetSymbolAddress((void**)&wlh,   g_wlm_h);

    cudaFuncSetAttribute(gemm_bf<0, false>,
        cudaFuncAttributeMaxDynamicSharedMemorySize, SMEM_BYTES);
    cudaFuncSetAttribute(gemm_bf<1, false>,
        cudaFuncAttributeMaxDynamicSharedMemorySize, SMEM_BYTES);
    cudaFuncSetAttribute(gemm_bf<2, true>,
        cudaFuncAttributeMaxDynamicSharedMemorySize, SMEM_BYTES);

    // ---- weight split (runs each call) ----
    {
        int n4;
        n4 = NL * ND * 3 * ND / 4;
        wsplit_kernel<<<(n4 + 255) / 256, 256>>>(Wqkv, wqh, wql, n4);
        n4 = NL * ND * ND / 4;
        wsplit_kernel<<<(n4 + 255) / 256, 256>>>(Wproj, wph, wpl, n4);
        n4 = NL * ND * NHID / 4;
        wsplit_kernel<<<(n4 + 255) / 256, 256>>>(Wg, wgh, wgl, n4);
        wsplit_kernel<<<(n4 + 255) / 256, 256>>>(Wu, wuh, wul, n4);
        n4 = NL * NHID * ND / 4;
        wsplit_kernel<<<(n4 + 255) / 256, 256>>>(Wd, wdh, wdl, n4);
        wconv_pad_f16_kernel<<<dim3((NVP + 255) / 256, ND), 256>>>(Wlm, wlh);
    }

    embed_kernel<<<MTOK, 256>>>(idx, wte, wpe, px);

    for (int l = 0; l < NL; l++) {
        rmsnorm_hl_kernel<<<MTOK, 256>>>(px, g1 + (size_t)l * ND, phh, phl);
        gemm_bf<0, false><<<dim3(3 * ND / BN, MTOK / BM), 256, SMEM_BYTES>>>(
            phh, phl, wqh + (size_t)l * ND * 3 * ND, wql + (size_t)l * ND * 3 * ND,
            nullptr, pqkv, nullptr, nullptr, MTOK, 3 * ND, 3 * ND, ND);
        attn_part_kernel<<<dim3(NB_ * NH, 32), 128>>>(pqkv, ppo, ppm, ppl);
        attn_merge_kernel<<<MTOK, 256>>>(ppo, ppm, ppl, pyh, pyl);
        gemm_bf<1, false><<<dim3(ND / BN, MTOK / BM), 256, SMEM_BYTES>>>(
            pyh, pyl, wph + (size_t)l * ND * ND, wpl + (size_t)l * ND * ND,
            px, px, nullptr, nullptr, MTOK, ND, ND, ND);
        rmsnorm_hl_kernel<<<MTOK, 256>>>(px, g2 + (size_t)l * ND, phh, phl);
        gemm_bf<0, false><<<dim3(NHID / BN, MTOK / BM), 256, SMEM_BYTES>>>(
            phh, phl, wgh + (size_t)l * ND * NHID, wgl + (size_t)l * ND * NHID,
            nullptr, pgate, nullptr, nullptr, MTOK, NHID, NHID, ND);
        gemm_bf<2, true><<<dim3(NHID / BN, MTOK / BM), 256, SMEM_BYTES>>>(
            phh, phl, wuh + (size_t)l * ND * NHID, wul + (size_t)l * ND * NHID,
            pgate, nullptr, psh, psl, MTOK, NHID, NHID, ND);
        gemm_bf<1, false><<<dim3(ND / BN, MTOK / BM), 256, SMEM_BYTES>>>(
            psh, psl, wdh + (size_t)l * NHID * ND, wdl + (size_t)l * NHID * ND,
            px, px, nullptr, nullptr, MTOK, ND, ND, NHID);
    }

    rmsnorm_f16_kernel<<<MTOK, 256>>>(px, gf, phh);
    gemm_f16<<<dim3(NVP / BN, MTOK / BM), 256>>>(
        phh, wlh, out, MTOK, NV, NVP, ND);
}

// round 15
// speedup vs baseline: 1.3746x; 1.0253x over previous
#include <cuda_runtime.h>
#include <cuda_fp16.h>
#include <math.h>
#include <stdint.h>

// Problem constants
#define NB_  2
#define NS   1024
#define ND   1024
#define NH   16
#define NDH  64
#define NL   12
#define NHID 2816
#define NV   50257
#define NVP  50304   // padded LM-head N (128*393)
#define MTOK 2048    // NB_*NS

// GEMM tiling: 128x128 block, BK=16, 8 warps (4m x 2n), warp tile 32x64
#define BM 128
#define BN 128
#define BK 16
#define STAGE_BYTES 16384
#define NSTAGE 4
#define SMEM_BYTES (NSTAGE * STAGE_BYTES)
#define PGRID 296   // persistent grid: 2 CTAs/SM x 148 SMs

// ---------------- activation scratch ----------------
__device__ float    g_x[MTOK * ND];            // residual (fp32)
__device__ uint16_t g_hh[MTOK * ND];           // rmsnorm out hi (bf16) / fp16 (final)
__device__ uint16_t g_hl[MTOK * ND];           // rmsnorm out lo
__device__ float    g_qkv[MTOK * 3 * ND];      // qkv (fp32)
__device__ uint16_t g_yh[MTOK * ND];           // attn out hi
__device__ uint16_t g_yl[MTOK * ND];           // attn out lo
__device__ float    g_gate[MTOK * NHID];       // gate pre-act (fp32)
__device__ uint16_t g_sh[MTOK * NHID];         // swiglu out hi
__device__ uint16_t g_sl[MTOK * NHID];         // swiglu out lo
// split-KV attention partials (2 halves)
__device__ float    g_po[2 * MTOK * ND];       // unnormalized o
__device__ float    g_pm[2 * MTOK * NH];       // running max
__device__ float    g_pl[2 * MTOK * NH];       // running sum

// ---------------- weight scratch ----------------
__device__ uint16_t g_wqkv_h[NL * ND * 3 * ND];
__device__ uint16_t g_wqkv_l[NL * ND * 3 * ND];
__device__ uint16_t g_wproj_h[NL * ND * ND];
__device__ uint16_t g_wproj_l[NL * ND * ND];
__device__ uint16_t g_wg_h[NL * ND * NHID];
__device__ uint16_t g_wg_l[NL * ND * NHID];
__device__ uint16_t g_wu_h[NL * ND * NHID];
__device__ uint16_t g_wu_l[NL * ND * NHID];
__device__ uint16_t g_wd_h[NL * NHID * ND];
__device__ uint16_t g_wd_l[NL * NHID * ND];
__device__ uint16_t g_wlm_h[ND * NVP];         // fp16 (single precision pass)

// ---------------- helpers ----------------
// A tile smem: 128 rows x 16 bf16 (32B/row), chunk-swizzled for LDSM
__device__ __forceinline__ uint32_t a_off(int m, int k) {
    uint32_t chunk = ((uint32_t)(k >> 3) ^ ((uint32_t)(m >> 2) & 1u)) & 1u;
    return (uint32_t)m * 32u + chunk * 16u + (uint32_t)(k & 7) * 2u;
}
// B tile smem: 16 rows x 128 bf16 (256B/row), chunk-swizzled for LDSM.trans
__device__ __forceinline__ uint32_t b_off(int k, int n) {
    uint32_t nb = (uint32_t)(n >> 3);
    uint32_t chunk = (nb & 8u) | ((nb ^ ((uint32_t)k & 7u)) & 7u);
    return (uint32_t)k * 256u + chunk * 16u + (uint32_t)(n & 7) * 2u;
}

__device__ __forceinline__ void ldsm4(uint32_t* r, uint32_t addr) {
    asm volatile("ldmatrix.sync.aligned.m8n8.x4.shared.b16 {%0,%1,%2,%3}, [%4];"
        : "=r"(r[0]), "=r"(r[1]), "=r"(r[2]), "=r"(r[3]) : "r"(addr));
}
__device__ __forceinline__ void ldsm4t(uint32_t* r, uint32_t addr) {
    asm volatile("ldmatrix.sync.aligned.m8n8.x4.trans.shared.b16 {%0,%1,%2,%3}, [%4];"
        : "=r"(r[0]), "=r"(r[1]), "=r"(r[2]), "=r"(r[3]) : "r"(addr));
}
#define MMA_BF16(acc, a, b0, b1)                                              \
    asm volatile(                                                              \
        "mma.sync.aligned.m16n8k16.row.col.f32.bf16.bf16.f32 "                 \
        "{%0,%1,%2,%3}, {%4,%5,%6,%7}, {%8,%9}, {%0,%1,%2,%3};"                \
        : "+f"(acc[0]), "+f"(acc[1]), "+f"(acc[2]), "+f"(acc[3])               \
        : "r"(a[0]), "r"(a[1]), "r"(a[2]), "r"(a[3]), "r"(b0), "r"(b1))

#define MMA_F16(acc, a, b0, b1)                                               \
    asm volatile(                                                              \
        "mma.sync.aligned.m16n8k16.row.col.f32.f16.f16.f32 "                   \
        "{%0,%1,%2,%3}, {%4,%5,%6,%7}, {%8,%9}, {%0,%1,%2,%3};"                \
        : "+f"(acc[0]), "+f"(acc[1]), "+f"(acc[2]), "+f"(acc[3])               \
        : "r"(a[0]), "r"(a[1]), "r"(a[2]), "r"(a[3]), "r"(b0), "r"(b1))

#define CPASYNC16(dst, src)                                                    \
    asm volatile("cp.async.cg.shared.global [%0], [%1], 16;"                   \
                 :: "r"(dst), "l"(src))

// split float4 into bf16x4 hi (rn) + lo (rn of residual)
__device__ __forceinline__ void split4(float4 v, uint2& hi, uint2& lo) {
    uint32_t h0, h1, l0, l1;
    asm("cvt.rn.bf16x2.f32 %0, %1, %2;" : "=r"(h0) : "f"(v.y), "f"(v.x));
    asm("cvt.rn.bf16x2.f32 %0, %1, %2;" : "=r"(h1) : "f"(v.w), "f"(v.z));
    float hx = __uint_as_float(h0 << 16);
    float hy = __uint_as_float(h0 & 0xffff0000u);
    float hz = __uint_as_float(h1 << 16);
    float hw = __uint_as_float(h1 & 0xffff0000u);
    float lx = v.x - hx, ly = v.y - hy, lz = v.z - hz, lw = v.w - hw;
    asm("cvt.rn.bf16x2.f32 %0, %1, %2;" : "=r"(l0) : "f"(ly), "f"(lx));
    asm("cvt.rn.bf16x2.f32 %0, %1, %2;" : "=r"(l1) : "f"(lw), "f"(lz));
    hi.x = h0; hi.y = h1; lo.x = l0; lo.y = l1;
}
// split pair (a=elem0, b=elem1) into hi/lo bf16x2 words
__device__ __forceinline__ void split2(float a, float b, uint32_t& h, uint32_t& l) {
    asm("cvt.rn.bf16x2.f32 %0, %1, %2;" : "=r"(h) : "f"(b), "f"(a));
    float ha = __uint_as_float(h << 16);
    float hb = __uint_as_float(h & 0xffff0000u);
    asm("cvt.rn.bf16x2.f32 %0, %1, %2;" : "=r"(l) : "f"(b - hb), "f"(a - ha));
}

// ---------------- weight split kernels ----------------
__global__ void wsplit_kernel(const float* __restrict__ w,
                              uint16_t* __restrict__ wh,
                              uint16_t* __restrict__ wl, int n4) {
    int i = blockIdx.x * 256 + threadIdx.x;
    if (i < n4) {
        float4 v = ((const float4*)w)[i];
        uint2 hi, lo;
        split4(v, hi, lo);
        ((uint2*)wh)[i] = hi;
        ((uint2*)wl)[i] = lo;
    }
}
// LM head: pad [1024,50257] -> [1024,50304] with zeros, convert to fp16
__global__ void wconv_pad_f16_kernel(const float* __restrict__ w,
                                     uint16_t* __restrict__ wh) {
    int c = blockIdx.x * 256 + threadIdx.x;
    int r = blockIdx.y;
    if (c < NVP) {
        float x = (c < NV) ? w[(size_t)r * NV + c] : 0.0f;
        wh[(size_t)r * NVP + c] = __half_as_ushort(__float2half_rn(x));
    }
}

// ---------------- embedding ----------------
__global__ void embed_kernel(const int* __restrict__ idx,
                             const float* __restrict__ wte,
                             const float* __restrict__ wpe,
                             float* __restrict__ x) {
    int row = blockIdx.x;
    int t = threadIdx.x;
    int tok = idx[row];
    int spos = row & (NS - 1);
    float4 a = ((const float4*)(wte + (size_t)tok * ND))[t];
    float4 b = ((const float4*)(wpe + (size_t)spos * ND))[t];
    float4 o;
    o.x = a.x + b.x; o.y = a.y + b.y; o.z = a.z + b.z; o.w = a.w + b.w;
    ((float4*)(x + (size_t)row * ND))[t] = o;
}

// ---------------- rmsnorm -> bf16 hi/lo ----------------
__global__ void rmsnorm_hl_kernel(const float* __restrict__ in,
                                  const float* __restrict__ gamma,
                                  uint16_t* __restrict__ oh,
                                  uint16_t* __restrict__ ol) {
    int row = blockIdx.x;
    int t = threadIdx.x;
    float4 v = ((const float4*)(in + (size_t)row * ND))[t];
    float ss = v.x * v.x + v.y * v.y + v.z * v.z + v.w * v.w;
    #pragma unroll
    for (int off = 16; off; off >>= 1)
        ss += __shfl_xor_sync(0xFFFFFFFFu, ss, off);
    __shared__ float red[8];
    if ((t & 31) == 0) red[t >> 5] = ss;
    __syncthreads();
    float tot = red[0] + red[1] + red[2] + red[3] +
                red[4] + red[5] + red[6] + red[7];
    float r = rsqrtf(tot * (1.0f / (float)ND) + 1e-12f);
    float4 g = ((const float4*)gamma)[t];
    float4 o;
    o.x = v.x * r * g.x; o.y = v.y * r * g.y;
    o.z = v.z * r * g.z; o.w = v.w * r * g.w;
    uint2 hi, lo;
    split4(o, hi, lo);
    ((uint2*)oh)[row * 256 + t] = hi;
    ((uint2*)ol)[row * 256 + t] = lo;
}

// ---------------- rmsnorm -> fp16 (final norm, feeds fp16 LM head) --------
__global__ void rmsnorm_f16_kernel(const float* __restrict__ in,
                                   const float* __restrict__ gamma,
                                   uint16_t* __restrict__ oh) {
    int row = blockIdx.x;
    int t = threadIdx.x;
    float4 v = ((const float4*)(in + (size_t)row * ND))[t];
    float ss = v.x * v.x + v.y * v.y + v.z * v.z + v.w * v.w;
    #pragma unroll
    for (int off = 16; off; off >>= 1)
        ss += __shfl_xor_sync(0xFFFFFFFFu, ss, off);
    __shared__ float red[8];
    if ((t & 31) == 0) red[t >> 5] = ss;
    __syncthreads();
    float tot = red[0] + red[1] + red[2] + red[3] +
                red[4] + red[5] + red[6] + red[7];
    float r = rsqrtf(tot * (1.0f / (float)ND) + 1e-12f);
    float4 g = ((const float4*)gamma)[t];
    __half2 p0 = __floats2half2_rn(v.x * r * g.x, v.y * r * g.y);
    __half2 p1 = __floats2half2_rn(v.z * r * g.z, v.w * r * g.w);
    uint2 o;
    o.x = *(uint32_t*)&p0;
    o.y = *(uint32_t*)&p1;
    ((uint2*)oh)[row * 256 + t] = o;
}

// ---------------- bf16 tensor-core GEMM, cp.async 4-stage, PERSISTENT ------
// C[M,N] = epi(A[M,K] @ B[K,N]) with A,B given as bf16 hi/lo pairs.
// EPI 0: C = acc (fp32) ; EPI 1: C = X + acc (fp32) ; EPI 2: silu(X)*acc
// OUTHL: write result as bf16 hi/lo to Oh/Ol instead of fp32 C.
// Persistent: 1-D grid, each block loops over tile ids stride gridDim.x.
template<int EPI, bool OUTHL>
__global__ __launch_bounds__(256, 2)
void gemm_bf(const uint16_t* __restrict__ Ah, const uint16_t* __restrict__ Al,
             const uint16_t* __restrict__ Bh, const uint16_t* __restrict__ Bl,
             const float* __restrict__ X, float* __restrict__ C,
             uint16_t* __restrict__ Oh, uint16_t* __restrict__ Ol,
             int M, int N, int NBs, int K) {
    extern __shared__ __align__(16) char sm[];
    const uint32_t sb = (uint32_t)__cvta_generic_to_shared(sm);

    const int tid  = threadIdx.x;
    const int lane = tid & 31;
    const int warp = tid >> 5;
    const int wm = warp & 3;
    const int wn = warp >> 2;
    const int lq = lane >> 2;
    const int lr = lane & 3;

    const int am = tid >> 1;
    const int ak = (tid & 1) * 8;
    const int bk = tid >> 4;
    const int bn = (tid & 15) * 8;
    const uint32_t a_dst = a_off(am, ak);
    const uint32_t b_dst = b_off(bk, bn);
    const int lid8 = lane >> 3;
    const int lrow = lane & 7;

    const int nbx = N / BN;
    const int ntile = nbx * (M / BM);
    const int ntk = K / BK;

    for (int t = blockIdx.x; t < ntile; t += gridDim.x) {
        const int m0 = (t / nbx) * BM;
        const int n0 = (t % nbx) * BN;

        float c[2][8][4];
        #pragma unroll
        for (int i = 0; i < 2; i++)
            #pragma unroll
            for (int j = 0; j < 8; j++)
                #pragma unroll
                for (int k = 0; k < 4; k++) c[i][j][k] = 0.0f;

        auto issue = [&](int kt) {
            const int kbase = kt * BK;
            const uint32_t stg = sb + (uint32_t)(kt & 3) * (uint32_t)STAGE_BYTES;
            CPASYNC16(stg + a_dst, Ah + (size_t)(m0 + am) * K + kbase + ak);
            CPASYNC16(stg + 4096u + a_dst, Al + (size_t)(m0 + am) * K + kbase + ak);
            CPASYNC16(stg + 8192u + b_dst, Bh + (size_t)(kbase + bk) * NBs + n0 + bn);
            CPASYNC16(stg + 12288u + b_dst, Bl + (size_t)(kbase + bk) * NBs + n0 + bn);
            asm volatile("cp.async.commit_group;" ::: "memory");
        };

        auto compute = [&](int buf) {
            const uint32_t ah_base = sb + (uint32_t)buf * (uint32_t)STAGE_BYTES;
            const uint32_t al_base = ah_base + 4096u;
            const uint32_t bh_base = ah_base + 8192u;
            const uint32_t bl_base = ah_base + 12288u;

            uint32_t ah[2][4], al[2][4];
            {
                int m = ((lid8 & 1) << 3) + lrow;
                int k = (lid8 >> 1) << 3;
                #pragma unroll
                for (int mf = 0; mf < 2; mf++) {
                    uint32_t off = a_off(wm * 32 + mf * 16 + m, k);
                    ldsm4(ah[mf], ah_base + off);
                    ldsm4(al[mf], al_base + off);
                }
            }
            #pragma unroll
            for (int h = 0; h < 2; h++) {
                uint32_t bhf[4][2], blf[4][2];
                #pragma unroll
                for (int j = 0; j < 2; j++) {
                    int k  = ((lid8 & 1) << 3) + lrow;
                    int nb = wn * 8 + h * 4 + j * 2 + (lid8 >> 1);
                    uint32_t off = b_off(k, nb << 3);
                    uint32_t rr[4];
                    ldsm4t(rr, bh_base + off);
                    bhf[j * 2][0] = rr[0]; bhf[j * 2][1] = rr[1];
                    bhf[j * 2 + 1][0] = rr[2]; bhf[j * 2 + 1][1] = rr[3];
                    ldsm4t(rr, bl_base + off);
                    blf[j * 2][0] = rr[0]; blf[j * 2][1] = rr[1];
                    blf[j * 2 + 1][0] = rr[2]; blf[j * 2 + 1][1] = rr[3];
                }
                #pragma unroll
                for (int mf = 0; mf < 2; mf++)
                    #pragma unroll
                    for (int j = 0; j < 4; j++) {
                        int nf = h * 4 + j;
                        MMA_BF16(c[mf][nf], ah[mf], bhf[j][0], bhf[j][1]);
                        MMA_BF16(c[mf][nf], ah[mf], blf[j][0], blf[j][1]);
                        MMA_BF16(c[mf][nf], al[mf], bhf[j][0], bhf[j][1]);
                    }
            }
        };

        issue(0); issue(1); issue(2);
        for (int kt = 0; kt < ntk; kt++) {
            asm volatile("cp.async.wait_group 2;" ::: "memory");
            __syncthreads();
            compute(kt & 3);
            if (kt + 3 < ntk) issue(kt + 3);
            else asm volatile("cp.async.commit_group;" ::: "memory");
        }
        // drain pipeline + barrier so next tile may reuse smem buffers
        asm volatile("cp.async.wait_group 0;" ::: "memory");
        __syncthreads();

        // ---- epilogue (gmem only) ----
        #pragma unroll
        for (int mf = 0; mf < 2; mf++) {
            int r0 = m0 + wm * 32 + mf * 16 + lq;
            int r1 = r0 + 8;
            #pragma unroll
            for (int nf = 0; nf < 8; nf++) {
                int col = n0 + wn * 64 + nf * 8 + 2 * lr;
                size_t o0 = (size_t)r0 * N + col;
                size_t o1 = (size_t)r1 * N + col;
                float2 v0 = make_float2(c[mf][nf][0], c[mf][nf][1]);
                float2 v1 = make_float2(c[mf][nf][2], c[mf][nf][3]);
                if (EPI == 1) {
                    float2 x0 = *(const float2*)(X + o0);
                    float2 x1 = *(const float2*)(X + o1);
                    v0.x += x0.x; v0.y += x0.y; v1.x += x1.x; v1.y += x1.y;
                } else if (EPI == 2) {
                    float2 x0 = *(const float2*)(X + o0);
                    float2 x1 = *(const float2*)(X + o1);
                    v0.x *= x0.x / (1.0f + __expf(-x0.x));
                    v0.y *= x0.y / (1.0f + __expf(-x0.y));
                    v1.x *= x1.x / (1.0f + __expf(-x1.x));
                    v1.y *= x1.y / (1.0f + __expf(-x1.y));
                }
                if (OUTHL) {
                    uint32_t h0, l0, h1, l1;
                    split2(v0.x, v0.y, h0, l0);
                    split2(v1.x, v1.y, h1, l1);
                    *(uint32_t*)(Oh + o0) = h0;
                    *(uint32_t*)(Ol + o0) = l0;
                    *(uint32_t*)(Oh + o1) = h1;
                    *(uint32_t*)(Ol + o1) = l1;
                } else {
                    *(float2*)(C + o0) = v0;
                    *(float2*)(C + o1) = v1;
                }
            }
        }
    }
}

// ---------------- fp16 single-pass GEMM (LM head), PERSISTENT --------------
// C[M,N] = A[M,K] @ B[K,N], A/B fp16. N may be odd (scalar store path).
#define F16_STAGE 8192
__global__ __launch_bounds__(256, 2)
void gemm_f16(const uint16_t* __restrict__ A, const uint16_t* __restrict__ B,
              float* __restrict__ C, int M, int N, int NBs, int K) {
    __shared__ __align__(16) char sm[NSTAGE * F16_STAGE];
    const uint32_t sb = (uint32_t)__cvta_generic_to_shared(sm);

    const int tid  = threadIdx.x;
    const int lane = tid & 31;
    const int warp = tid >> 5;
    const int wm = warp & 3;
    const int wn = warp >> 2;
    const int lq = lane >> 2;
    const int lr = lane & 3;

    const int am = tid >> 1;
    const int ak = (tid & 1) * 8;
    const int bk = tid >> 4;
    const int bn = (tid & 15) * 8;
    const uint32_t a_dst = a_off(am, ak);
    const uint32_t b_dst = b_off(bk, bn);
    const int lid8 = lane >> 3;
    const int lrow = lane & 7;

    const int nbx = NBs / BN;
    const int ntile = nbx * (M / BM);
    const int ntk = K / BK;
    const bool evenN = ((N & 1) == 0);

    for (int t = blockIdx.x; t < ntile; t += gridDim.x) {
        const int m0 = (t / nbx) * BM;
        const int n0 = (t % nbx) * BN;

        float c[2][8][4];
        #pragma unroll
        for (int i = 0; i < 2; i++)
            #pragma unroll
            for (int j = 0; j < 8; j++)
                #pragma unroll
                for (int k = 0; k < 4; k++) c[i][j][k] = 0.0f;

        auto issue = [&](int kt) {
            const int kbase = kt * BK;
            const uint32_t stg = sb + (uint32_t)(kt & 3) * (uint32_t)F16_STAGE;
            CPASYNC16(stg + a_dst, A + (size_t)(m0 + am) * K + kbase + ak);
            CPASYNC16(stg + 4096u + b_dst, B + (size_t)(kbase + bk) * NBs + n0 + bn);
            asm volatile("cp.async.commit_group;" ::: "memory");
        };

        auto compute = [&](int buf) {
            const uint32_t a_base = sb + (uint32_t)buf * (uint32_t)F16_STAGE;
            const uint32_t b_base = a_base + 4096u;

            uint32_t af[2][4];
            {
                int m = ((lid8 & 1) << 3) + lrow;
                int k = (lid8 >> 1) << 3;
                #pragma unroll
                for (int mf = 0; mf < 2; mf++)
                    ldsm4(af[mf], a_base + a_off(wm * 32 + mf * 16 + m, k));
            }
            #pragma unroll
            for (int h = 0; h < 2; h++) {
                uint32_t bf[4][2];
                #pragma unroll
                for (int j = 0; j < 2; j++) {
                    int k  = ((lid8 & 1) << 3) + lrow;
                    int nb = wn * 8 + h * 4 + j * 2 + (lid8 >> 1);
                    uint32_t rr[4];
                    ldsm4t(rr, b_base + b_off(k, nb << 3));
                    bf[j * 2][0] = rr[0]; bf[j * 2][1] = rr[1];
                    bf[j * 2 + 1][0] = rr[2]; bf[j * 2 + 1][1] = rr[3];
                }
                #pragma unroll
                for (int mf = 0; mf < 2; mf++)
                    #pragma unroll
                    for (int j = 0; j < 4; j++)
                        MMA_F16(c[mf][h * 4 + j], af[mf], bf[j][0], bf[j][1]);
            }
        };

        issue(0); issue(1); issue(2);
        for (int kt = 0; kt < ntk; kt++) {
            asm volatile("cp.async.wait_group 2;" ::: "memory");
            __syncthreads();
            compute(kt & 3);
            if (kt + 3 < ntk) issue(kt + 3);
            else asm volatile("cp.async.commit_group;" ::: "memory");
        }
        asm volatile("cp.async.wait_group 0;" ::: "memory");
        __syncthreads();

        #pragma unroll
        for (int mf = 0; mf < 2; mf++) {
            int r0 = m0 + wm * 32 + mf * 16 + lq;
            int r1 = r0 + 8;
            #pragma unroll
            for (int nf = 0; nf < 8; nf++) {
                int col = n0 + wn * 64 + nf * 8 + 2 * lr;
                size_t o0 = (size_t)r0 * N + col;
                size_t o1 = (size_t)r1 * N + col;
                if (col + 2 <= N) {
                    if (evenN) {
                        *(float2*)(C + o0) = make_float2(c[mf][nf][0], c[mf][nf][1]);
                        *(float2*)(C + o1) = make_float2(c[mf][nf][2], c[mf][nf][3]);
                    } else {
                        C[o0] = c[mf][nf][0]; C[o0 + 1] = c[mf][nf][1];
                        C[o1] = c[mf][nf][2]; C[o1 + 1] = c[mf][nf][3];
                    }
                } else if (col < N) {
                    C[o0] = c[mf][nf][0];
                    C[o1] = c[mf][nf][2];
                }
            }
        }
    }
}

// ---------------- split-KV flash attention (causal, fp32) ------------------
__global__ __launch_bounds__(128)
void attn_part_kernel(const float* __restrict__ qkv,
                      float* __restrict__ po,
                      float* __restrict__ pm,
                      float* __restrict__ pl) {
    const int bh = blockIdx.x;
    const int b  = bh >> 4;
    const int hd = bh & 15;
    const int qg   = 15 - (blockIdx.y >> 1);
    const int half = blockIdx.y & 1;
    const int tid = threadIdx.x;
    const int row = tid >> 1;
    const int hdim = tid & 1;
    const int qrow = qg * 64 + row;
    const int doff = hdim * 4;

    const float* qptr = qkv + ((size_t)(b * NS + qrow) * (3 * ND)) + hd * NDH;
    float4 q[8];
    #pragma unroll
    for (int i = 0; i < 8; i++)
        q[i] = *(const float4*)(qptr + i * 8 + doff);

    float4 o[8];
    #pragma unroll
    for (int i = 0; i < 8; i++) o[i] = make_float4(0.f, 0.f, 0.f, 0.f);
    float m = -1e30f, l = 0.0f;

    __shared__ float ksm[64][64];
    __shared__ float vsm[64][64];

    const int ntiles = qg + 1;
    for (int kt = half; kt < ntiles; kt += 2) {
        const int kbase = kt * 64;
        #pragma unroll
        for (int i = 0; i < 8; i++) {
            int li = tid + i * 128;
            int r  = li >> 4;
            int c4 = (li & 15) * 4;
            const float* base = qkv + ((size_t)(b * NS + kbase + r) * (3 * ND))
                                + hd * NDH + c4;
            *(float4*)&ksm[r][c4] = *(const float4*)(base + ND);
            *(float4*)&vsm[r][c4] = *(const float4*)(base + 2 * ND);
        }
        __syncthreads();

        #pragma unroll 1
        for (int jt = 0; jt < 4; jt++) {
            float s[16];
            #pragma unroll
            for (int j = 0; j < 16; j++) {
                int jr = jt * 16 + j;
                float a = 0.0f;
                #pragma unroll
                for (int i = 0; i < 8; i++) {
                    float4 kv = *(const float4*)&ksm[jr][i * 8 + doff];
                    a += q[i].x * kv.x + q[i].y * kv.y
                       + q[i].z * kv.z + q[i].w * kv.w;
                }
                a += __shfl_xor_sync(0xFFFFFFFFu, a, 1);
                int key = kbase + jr;
                s[j] = (key <= qrow) ? a * 0.125f : -1e30f;
            }
            float tm = s[0];
            #pragma unroll
            for (int j = 1; j < 16; j++) tm = fmaxf(tm, s[j]);
            float mnew = fmaxf(m, tm);
            float corr = __expf(m - mnew);
            float psum = 0.0f;
            #pragma unroll
            for (int j = 0; j < 16; j++) {
                s[j] = __expf(s[j] - mnew);
                psum += s[j];
            }
            l = l * corr + psum;
            m = mnew;
            #pragma unroll
            for (int i = 0; i < 8; i++) {
                o[i].x *= corr; o[i].y *= corr; o[i].z *= corr; o[i].w *= corr;
            }
            #pragma unroll
            for (int j = 0; j < 16; j++) {
                float p = s[j];
                int jr = jt * 16 + j;
                #pragma unroll
                for (int i = 0; i < 8; i++) {
                    float4 vv = *(const float4*)&vsm[jr][i * 8 + doff];
                    o[i].x += p * vv.x; o[i].y += p * vv.y;
                    o[i].z += p * vv.z; o[i].w += p * vv.w;
                }
            }
        }
        __syncthreads();
    }

    const size_t tok = (size_t)(b * NS + qrow);
    if (hdim == 0) {
        pm[(size_t)half * (MTOK * NH) + tok * NH + hd] = m;
        pl[(size_t)half * (MTOK * NH) + tok * NH + hd] = l;
    }
    float* op = po + (size_t)half * (MTOK * ND) + tok * ND + hd * NDH;
    #pragma unroll
    for (int i = 0; i < 8; i++)
        *(float4*)(op + i * 8 + doff) = o[i];
}

// ---------------- attention merge: combine 2 halves -> bf16 hi/lo ----------
__global__ __launch_bounds__(256)
void attn_merge_kernel(const float* __restrict__ po,
                       const float* __restrict__ pm,
                       const float* __restrict__ pl,
                       uint16_t* __restrict__ yh, uint16_t* __restrict__ yl) {
    const int tok = blockIdx.x;
    const int t = threadIdx.x;
    const int hd = t >> 4;
    const int d4 = (t & 15) * 4;

    float m1 = pm[(size_t)tok * NH + hd];
    float l1 = pl[(size_t)tok * NH + hd];
    float m2 = pm[(size_t)(MTOK * NH) + (size_t)tok * NH + hd];
    float l2 = pl[(size_t)(MTOK * NH) + (size_t)tok * NH + hd];
    float M = fmaxf(m1, m2);
    float s1 = __expf(m1 - M);
    float s2 = __expf(m2 - M);
    float inv = 1.0f / (l1 * s1 + l2 * s2);

    size_t off = (size_t)tok * ND + hd * NDH + d4;
    float4 o1 = *(const float4*)(po + off);
    float4 o2 = *(const float4*)(po + (size_t)(MTOK * ND) + off);
    float4 r;
    r.x = (o1.x * s1 + o2.x * s2) * inv;
    r.y = (o1.y * s1 + o2.y * s2) * inv;
    r.z = (o1.z * s1 + o2.z * s2) * inv;
    r.w = (o1.w * s1 + o2.w * s2) * inv;
    uint2 hi, lo;
    split4(r, hi, lo);
    *(uint2*)(yh + off) = hi;
    *(uint2*)(yl + off) = lo;
}

// ---------------- launch ----------------
static inline int pgrid(int tiles) { return tiles < PGRID ? tiles : PGRID; }

extern "C" void kernel_launch(void* const* d_in, const int* in_sizes, int n_in,
                              void* d_out, int out_size) {
    const int*   idx   = (const int*)  d_in[0];
    const float* wte   = (const float*)d_in[1];
    const float* wpe   = (const float*)d_in[2];
    const float* g1    = (const float*)d_in[3];
    const float* Wqkv  = (const float*)d_in[4];
    const float* Wproj = (const float*)d_in[5];
    const float* g2    = (const float*)d_in[6];
    const float* Wg    = (const float*)d_in[7];
    const float* Wu    = (const float*)d_in[8];
    const float* Wd    = (const float*)d_in[9];
    const float* gf    = (const float*)d_in[10];
    const float* Wlm   = (const float*)d_in[11];
    float* out = (float*)d_out;

    float *px, *pqkv, *pgate, *ppo, *ppm, *ppl;
    uint16_t *phh, *phl, *pyh, *pyl, *psh, *psl;
    uint16_t *wqh, *wql, *wph, *wpl, *wgh, *wgl, *wuh, *wul, *wdh, *wdl, *wlh;
    cudaGetSymbolAddress((void**)&px,    g_x);
    cudaGetSymbolAddress((void**)&pqkv,  g_qkv);
    cudaGetSymbolAddress((void**)&pgate, g_gate);
    cudaGetSymbolAddress((void**)&ppo,   g_po);
    cudaGetSymbolAddress((void**)&ppm,   g_pm);
    cudaGetSymbolAddress((void**)&ppl,   g_pl);
    cudaGetSymbolAddress((void**)&phh,   g_hh);
    cudaGetSymbolAddress((void**)&phl,   g_hl);
    cudaGetSymbolAddress((void**)&pyh,   g_yh);
    cudaGetSymbolAddress((void**)&pyl,   g_yl);
    cudaGetSymbolAddress((void**)&psh,   g_sh);
    cudaGetSymbolAddress((void**)&psl,   g_sl);
    cudaGetSymbolAddress((void**)&wqh,   g_wqkv_h);
    cudaGetSymbolAddress((void**)&wql,   g_wqkv_l);
    cudaGetSymbolAddress((void**)&wph,   g_wproj_h);
    cudaGetSymbolAddress((void**)&wpl,   g_wproj_l);
    cudaGetSymbolAddress((void**)&wgh,   g_wg_h);
    cudaGetSymbolAddress((void**)&wgl,   g_wg_l);
    cudaGetSymbolAddress((void**)&wuh,   g_wu_h);
    cudaGetSymbolAddress((void**)&wul,   g_wu_l);
    cudaGetSymbolAddress((void**)&wdh,   g_wd_h);
    cudaGetSymbolAddress((void**)&wdl,   g_wd_l);
    cudaGetSymbolAddress((void**)&wlh,   g_wlm_h);

    cudaFuncSetAttribute(gemm_bf<0, false>,
        cudaFuncAttributeMaxDynamicSharedMemorySize, SMEM_BYTES);
    cudaFuncSetAttribute(gemm_bf<1, false>,
        cudaFuncAttributeMaxDynamicSharedMemorySize, SMEM_BYTES);
    cudaFuncSetAttribute(gemm_bf<2, true>,
        cudaFuncAttributeMaxDynamicSharedMemorySize, SMEM_BYTES);

    // ---- weight split (runs each call) ----
    {
        int n4;
        n4 = NL * ND * 3 * ND / 4;
        wsplit_kernel<<<(n4 + 255) / 256, 256>>>(Wqkv, wqh, wql, n4);
        n4 = NL * ND * ND / 4;
        wsplit_kernel<<<(n4 + 255) / 256, 256>>>(Wproj, wph, wpl, n4);
        n4 = NL * ND * NHID / 4;
        wsplit_kernel<<<(n4 + 255) / 256, 256>>>(Wg, wgh, wgl, n4);
        wsplit_kernel<<<(n4 + 255) / 256, 256>>>(Wu, wuh, wul, n4);
        n4 = NL * NHID * ND / 4;
        wsplit_kernel<<<(n4 + 255) / 256, 256>>>(Wd, wdh, wdl, n4);
        wconv_pad_f16_kernel<<<dim3((NVP + 255) / 256, ND), 256>>>(Wlm, wlh);
    }

    embed_kernel<<<MTOK, 256>>>(idx, wte, wpe, px);

    const int t_qkv  = (3 * ND / BN) * (MTOK / BM);   // 24*16 = 384
    const int t_sq   = (ND / BN) * (MTOK / BM);       // 8*16  = 128
    const int t_ffn  = (NHID / BN) * (MTOK / BM);     // 22*16 = 352
    const int t_lm   = (NVP / BN) * (MTOK / BM);      // 393*16

    for (int l = 0; l < NL; l++) {
        rmsnorm_hl_kernel<<<MTOK, 256>>>(px, g1 + (size_t)l * ND, phh, phl);
        gemm_bf<0, false><<<pgrid(t_qkv), 256, SMEM_BYTES>>>(
            phh, phl, wqh + (size_t)l * ND * 3 * ND, wql + (size_t)l * ND * 3 * ND,
            nullptr, pqkv, nullptr, nullptr, MTOK, 3 * ND, 3 * ND, ND);
        attn_part_kernel<<<dim3(NB_ * NH, 32), 128>>>(pqkv, ppo, ppm, ppl);
        attn_merge_kernel<<<MTOK, 256>>>(ppo, ppm, ppl, pyh, pyl);
        gemm_bf<1, false><<<pgrid(t_sq), 256, SMEM_BYTES>>>(
            pyh, pyl, wph + (size_t)l * ND * ND, wpl + (size_t)l * ND * ND,
            px, px, nullptr, nullptr, MTOK, ND, ND, ND);
        rmsnorm_hl_kernel<<<MTOK, 256>>>(px, g2 + (size_t)l * ND, phh, phl);
        gemm_bf<0, false><<<pgrid(t_ffn), 256, SMEM_BYTES>>>(
            phh, phl, wgh + (size_t)l * ND * NHID, wgl + (size_t)l * ND * NHID,
            nullptr, pgate, nullptr, nullptr, MTOK, NHID, NHID, ND);
        gemm_bf<2, true><<<pgrid(t_ffn), 256, SMEM_BYTES>>>(
            phh, phl, wuh + (size_t)l * ND * NHID, wul + (size_t)l * ND * NHID,
            pgate, nullptr, psh, psl, MTOK, NHID, NHID, ND);
        gemm_bf<1, false><<<pgrid(t_sq), 256, SMEM_BYTES>>>(
            psh, psl, wdh + (size_t)l * NHID * ND, wdl + (size_t)l * NHID * ND,
            px, px, nullptr, nullptr, MTOK, ND, ND, NHID);
    }

    rmsnorm_f16_kernel<<<MTOK, 256>>>(px, gf, phh);
    gemm_f16<<<pgrid(t_lm), 256>>>(phh, wlh, out, MTOK, NV, NVP, ND);
}

// round 16
// speedup vs baseline: 1.4555x; 1.0589x over previous
#include <cuda_runtime.h>
#include <cuda_fp16.h>
#include <math.h>
#include <stdint.h>

// Problem constants
#define NB_  2
#define NS   1024
#define ND   1024
#define NH   16
#define NDH  64
#define NL   12
#define NHID 2816
#define NV   50257
#define NVP  50304   // padded LM-head N (128*393)
#define MTOK 2048    // NB_*NS

// GEMM tiling: 128x128 block, BK=16, 8 warps (4m x 2n), warp tile 32x64
#define BM 128
#define BN 128
#define BK 16
#define STAGE_BYTES 16384
#define NSTAGE 4
#define SMEM_BYTES (NSTAGE * STAGE_BYTES)
#define PGRID 296   // persistent grid: 2 CTAs/SM x 148 SMs
#define KSPLIT 4    // attention KV split

// ---------------- activation scratch ----------------
__device__ float    g_x[MTOK * ND];            // residual (fp32)
__device__ uint16_t g_hh[MTOK * ND];           // rmsnorm out hi (bf16) / fp16 (final)
__device__ uint16_t g_hl[MTOK * ND];           // rmsnorm out lo
__device__ float    g_qkv[MTOK * 3 * ND];      // qkv (fp32)
__device__ uint16_t g_yh[MTOK * ND];           // attn out hi
__device__ uint16_t g_yl[MTOK * ND];           // attn out lo
__device__ uint16_t g_sh[MTOK * NHID];         // swiglu out hi
__device__ uint16_t g_sl[MTOK * NHID];         // swiglu out lo
// split-KV attention partials (KSPLIT quarters)
__device__ float    g_po[KSPLIT * MTOK * ND];  // unnormalized o
__device__ float    g_pm[KSPLIT * MTOK * NH];  // running max
__device__ float    g_pl[KSPLIT * MTOK * NH];  // running sum

// ---------------- weight scratch ----------------
__device__ uint16_t g_wqkv_h[NL * ND * 3 * ND];
__device__ uint16_t g_wqkv_l[NL * ND * 3 * ND];
__device__ uint16_t g_wproj_h[NL * ND * ND];
__device__ uint16_t g_wproj_l[NL * ND * ND];
__device__ uint16_t g_wg_h[NL * ND * NHID];
__device__ uint16_t g_wg_l[NL * ND * NHID];
__device__ uint16_t g_wu_h[NL * ND * NHID];
__device__ uint16_t g_wu_l[NL * ND * NHID];
__device__ uint16_t g_wd_h[NL * NHID * ND];
__device__ uint16_t g_wd_l[NL * NHID * ND];
__device__ uint16_t g_wlm_h[ND * NVP];         // fp16 (single precision pass)

// ---------------- helpers ----------------
// A tile smem: 128 rows x 16 bf16 (32B/row), chunk-swizzled for LDSM
__device__ __forceinline__ uint32_t a_off(int m, int k) {
    uint32_t chunk = ((uint32_t)(k >> 3) ^ ((uint32_t)(m >> 2) & 1u)) & 1u;
    return (uint32_t)m * 32u + chunk * 16u + (uint32_t)(k & 7) * 2u;
}
// B tile smem: 16 rows x 128 bf16 (256B/row), chunk-swizzled for LDSM.trans
__device__ __forceinline__ uint32_t b_off(int k, int n) {
    uint32_t nb = (uint32_t)(n >> 3);
    uint32_t chunk = (nb & 8u) | ((nb ^ ((uint32_t)k & 7u)) & 7u);
    return (uint32_t)k * 256u + chunk * 16u + (uint32_t)(n & 7) * 2u;
}
// B64 tile smem: 16 rows x 64 bf16 (128B/row), chunk-swizzled for LDSM.trans
__device__ __forceinline__ uint32_t b64_off(int k, int n) {
    uint32_t nb = (uint32_t)(n >> 3);
    uint32_t chunk = (nb ^ ((uint32_t)k & 7u)) & 7u;
    return (uint32_t)k * 128u + chunk * 16u + (uint32_t)(n & 7) * 2u;
}

__device__ __forceinline__ void ldsm4(uint32_t* r, uint32_t addr) {
    asm volatile("ldmatrix.sync.aligned.m8n8.x4.shared.b16 {%0,%1,%2,%3}, [%4];"
        : "=r"(r[0]), "=r"(r[1]), "=r"(r[2]), "=r"(r[3]) : "r"(addr));
}
__device__ __forceinline__ void ldsm4t(uint32_t* r, uint32_t addr) {
    asm volatile("ldmatrix.sync.aligned.m8n8.x4.trans.shared.b16 {%0,%1,%2,%3}, [%4];"
        : "=r"(r[0]), "=r"(r[1]), "=r"(r[2]), "=r"(r[3]) : "r"(addr));
}
#define MMA_BF16(acc, a, b0, b1)                                              \
    asm volatile(                                                              \
        "mma.sync.aligned.m16n8k16.row.col.f32.bf16.bf16.f32 "                 \
        "{%0,%1,%2,%3}, {%4,%5,%6,%7}, {%8,%9}, {%0,%1,%2,%3};"                \
        : "+f"(acc[0]), "+f"(acc[1]), "+f"(acc[2]), "+f"(acc[3])               \
        : "r"(a[0]), "r"(a[1]), "r"(a[2]), "r"(a[3]), "r"(b0), "r"(b1))

#define MMA_F16(acc, a, b0, b1)                                               \
    asm volatile(                                                              \
        "mma.sync.aligned.m16n8k16.row.col.f32.f16.f16.f32 "                   \
        "{%0,%1,%2,%3}, {%4,%5,%6,%7}, {%8,%9}, {%0,%1,%2,%3};"                \
        : "+f"(acc[0]), "+f"(acc[1]), "+f"(acc[2]), "+f"(acc[3])               \
        : "r"(a[0]), "r"(a[1]), "r"(a[2]), "r"(a[3]), "r"(b0), "r"(b1))

#define CPASYNC16(dst, src)                                                    \
    asm volatile("cp.async.cg.shared.global [%0], [%1], 16;"                   \
                 :: "r"(dst), "l"(src))

// split float4 into bf16x4 hi (rn) + lo (rn of residual)
__device__ __forceinline__ void split4(float4 v, uint2& hi, uint2& lo) {
    uint32_t h0, h1, l0, l1;
    asm("cvt.rn.bf16x2.f32 %0, %1, %2;" : "=r"(h0) : "f"(v.y), "f"(v.x));
    asm("cvt.rn.bf16x2.f32 %0, %1, %2;" : "=r"(h1) : "f"(v.w), "f"(v.z));
    float hx = __uint_as_float(h0 << 16);
    float hy = __uint_as_float(h0 & 0xffff0000u);
    float hz = __uint_as_float(h1 << 16);
    float hw = __uint_as_float(h1 & 0xffff0000u);
    float lx = v.x - hx, ly = v.y - hy, lz = v.z - hz, lw = v.w - hw;
    asm("cvt.rn.bf16x2.f32 %0, %1, %2;" : "=r"(l0) : "f"(ly), "f"(lx));
    asm("cvt.rn.bf16x2.f32 %0, %1, %2;" : "=r"(l1) : "f"(lw), "f"(lz));
    hi.x = h0; hi.y = h1; lo.x = l0; lo.y = l1;
}
// split pair (a=elem0, b=elem1) into hi/lo bf16x2 words
__device__ __forceinline__ void split2(float a, float b, uint32_t& h, uint32_t& l) {
    asm("cvt.rn.bf16x2.f32 %0, %1, %2;" : "=r"(h) : "f"(b), "f"(a));
    float ha = __uint_as_float(h << 16);
    float hb = __uint_as_float(h & 0xffff0000u);
    asm("cvt.rn.bf16x2.f32 %0, %1, %2;" : "=r"(l) : "f"(b - hb), "f"(a - ha));
}

// ---------------- weight split kernels ----------------
__global__ void wsplit_kernel(const float* __restrict__ w,
                              uint16_t* __restrict__ wh,
                              uint16_t* __restrict__ wl, int n4) {
    int i = blockIdx.x * 256 + threadIdx.x;
    if (i < n4) {
        float4 v = ((const float4*)w)[i];
        uint2 hi, lo;
        split4(v, hi, lo);
        ((uint2*)wh)[i] = hi;
        ((uint2*)wl)[i] = lo;
    }
}
// LM head: pad [1024,50257] -> [1024,50304] with zeros, convert to fp16
__global__ void wconv_pad_f16_kernel(const float* __restrict__ w,
                                     uint16_t* __restrict__ wh) {
    int c = blockIdx.x * 256 + threadIdx.x;
    int r = blockIdx.y;
    if (c < NVP) {
        float x = (c < NV) ? w[(size_t)r * NV + c] : 0.0f;
        wh[(size_t)r * NVP + c] = __half_as_ushort(__float2half_rn(x));
    }
}

// ---------------- embedding ----------------
__global__ void embed_kernel(const int* __restrict__ idx,
                             const float* __restrict__ wte,
                             const float* __restrict__ wpe,
                             float* __restrict__ x) {
    int row = blockIdx.x;
    int t = threadIdx.x;
    int tok = idx[row];
    int spos = row & (NS - 1);
    float4 a = ((const float4*)(wte + (size_t)tok * ND))[t];
    float4 b = ((const float4*)(wpe + (size_t)spos * ND))[t];
    float4 o;
    o.x = a.x + b.x; o.y = a.y + b.y; o.z = a.z + b.z; o.w = a.w + b.w;
    ((float4*)(x + (size_t)row * ND))[t] = o;
}

// ---------------- rmsnorm -> bf16 hi/lo ----------------
__global__ void rmsnorm_hl_kernel(const float* __restrict__ in,
                                  const float* __restrict__ gamma,
                                  uint16_t* __restrict__ oh,
                                  uint16_t* __restrict__ ol) {
    int row = blockIdx.x;
    int t = threadIdx.x;
    float4 v = ((const float4*)(in + (size_t)row * ND))[t];
    float ss = v.x * v.x + v.y * v.y + v.z * v.z + v.w * v.w;
    #pragma unroll
    for (int off = 16; off; off >>= 1)
        ss += __shfl_xor_sync(0xFFFFFFFFu, ss, off);
    __shared__ float red[8];
    if ((t & 31) == 0) red[t >> 5] = ss;
    __syncthreads();
    float tot = red[0] + red[1] + red[2] + red[3] +
                red[4] + red[5] + red[6] + red[7];
    float r = rsqrtf(tot * (1.0f / (float)ND) + 1e-12f);
    float4 g = ((const float4*)gamma)[t];
    float4 o;
    o.x = v.x * r * g.x; o.y = v.y * r * g.y;
    o.z = v.z * r * g.z; o.w = v.w * r * g.w;
    uint2 hi, lo;
    split4(o, hi, lo);
    ((uint2*)oh)[row * 256 + t] = hi;
    ((uint2*)ol)[row * 256 + t] = lo;
}

// ---------------- rmsnorm -> fp16 (final norm, feeds fp16 LM head) --------
__global__ void rmsnorm_f16_kernel(const float* __restrict__ in,
                                   const float* __restrict__ gamma,
                                   uint16_t* __restrict__ oh) {
    int row = blockIdx.x;
    int t = threadIdx.x;
    float4 v = ((const float4*)(in + (size_t)row * ND))[t];
    float ss = v.x * v.x + v.y * v.y + v.z * v.z + v.w * v.w;
    #pragma unroll
    for (int off = 16; off; off >>= 1)
        ss += __shfl_xor_sync(0xFFFFFFFFu, ss, off);
    __shared__ float red[8];
    if ((t & 31) == 0) red[t >> 5] = ss;
    __syncthreads();
    float tot = red[0] + red[1] + red[2] + red[3] +
                red[4] + red[5] + red[6] + red[7];
    float r = rsqrtf(tot * (1.0f / (float)ND) + 1e-12f);
    float4 g = ((const float4*)gamma)[t];
    __half2 p0 = __floats2half2_rn(v.x * r * g.x, v.y * r * g.y);
    __half2 p1 = __floats2half2_rn(v.z * r * g.z, v.w * r * g.w);
    uint2 o;
    o.x = *(uint32_t*)&p0;
    o.y = *(uint32_t*)&p1;
    ((uint2*)oh)[row * 256 + t] = o;
}

// ---------------- bf16 tensor-core GEMM, cp.async 4-stage, PERSISTENT ------
// C[M,N] = epi(A[M,K] @ B[K,N]); EPI 0: acc ; EPI 1: X+acc
template<int EPI>
__global__ __launch_bounds__(256, 2)
void gemm_bf(const uint16_t* __restrict__ Ah, const uint16_t* __restrict__ Al,
             const uint16_t* __restrict__ Bh, const uint16_t* __restrict__ Bl,
             const float* __restrict__ X, float* __restrict__ C,
             int M, int N, int NBs, int K) {
    extern __shared__ __align__(16) char sm[];
    const uint32_t sb = (uint32_t)__cvta_generic_to_shared(sm);

    const int tid  = threadIdx.x;
    const int lane = tid & 31;
    const int warp = tid >> 5;
    const int wm = warp & 3;
    const int wn = warp >> 2;
    const int lq = lane >> 2;
    const int lr = lane & 3;

    const int am = tid >> 1;
    const int ak = (tid & 1) * 8;
    const int bk = tid >> 4;
    const int bn = (tid & 15) * 8;
    const uint32_t a_dst = a_off(am, ak);
    const uint32_t b_dst = b_off(bk, bn);
    const int lid8 = lane >> 3;
    const int lrow = lane & 7;

    const int nbx = N / BN;
    const int ntile = nbx * (M / BM);
    const int ntk = K / BK;

    for (int t = blockIdx.x; t < ntile; t += gridDim.x) {
        const int m0 = (t / nbx) * BM;
        const int n0 = (t % nbx) * BN;

        float c[2][8][4];
        #pragma unroll
        for (int i = 0; i < 2; i++)
            #pragma unroll
            for (int j = 0; j < 8; j++)
                #pragma unroll
                for (int k = 0; k < 4; k++) c[i][j][k] = 0.0f;

        auto issue = [&](int kt) {
            const int kbase = kt * BK;
            const uint32_t stg = sb + (uint32_t)(kt & 3) * (uint32_t)STAGE_BYTES;
            CPASYNC16(stg + a_dst, Ah + (size_t)(m0 + am) * K + kbase + ak);
            CPASYNC16(stg + 4096u + a_dst, Al + (size_t)(m0 + am) * K + kbase + ak);
            CPASYNC16(stg + 8192u + b_dst, Bh + (size_t)(kbase + bk) * NBs + n0 + bn);
            CPASYNC16(stg + 12288u + b_dst, Bl + (size_t)(kbase + bk) * NBs + n0 + bn);
            asm volatile("cp.async.commit_group;" ::: "memory");
        };

        auto compute = [&](int buf) {
            const uint32_t ah_base = sb + (uint32_t)buf * (uint32_t)STAGE_BYTES;
            const uint32_t al_base = ah_base + 4096u;
            const uint32_t bh_base = ah_base + 8192u;
            const uint32_t bl_base = ah_base + 12288u;

            uint32_t ah[2][4], al[2][4];
            {
                int m = ((lid8 & 1) << 3) + lrow;
                int k = (lid8 >> 1) << 3;
                #pragma unroll
                for (int mf = 0; mf < 2; mf++) {
                    uint32_t off = a_off(wm * 32 + mf * 16 + m, k);
                    ldsm4(ah[mf], ah_base + off);
                    ldsm4(al[mf], al_base + off);
                }
            }
            #pragma unroll
            for (int h = 0; h < 2; h++) {
                uint32_t bhf[4][2], blf[4][2];
                #pragma unroll
                for (int j = 0; j < 2; j++) {
                    int k  = ((lid8 & 1) << 3) + lrow;
                    int nb = wn * 8 + h * 4 + j * 2 + (lid8 >> 1);
                    uint32_t off = b_off(k, nb << 3);
                    uint32_t rr[4];
                    ldsm4t(rr, bh_base + off);
                    bhf[j * 2][0] = rr[0]; bhf[j * 2][1] = rr[1];
                    bhf[j * 2 + 1][0] = rr[2]; bhf[j * 2 + 1][1] = rr[3];
                    ldsm4t(rr, bl_base + off);
                    blf[j * 2][0] = rr[0]; blf[j * 2][1] = rr[1];
                    blf[j * 2 + 1][0] = rr[2]; blf[j * 2 + 1][1] = rr[3];
                }
                #pragma unroll
                for (int mf = 0; mf < 2; mf++)
                    #pragma unroll
                    for (int j = 0; j < 4; j++) {
                        int nf = h * 4 + j;
                        MMA_BF16(c[mf][nf], ah[mf], bhf[j][0], bhf[j][1]);
                        MMA_BF16(c[mf][nf], ah[mf], blf[j][0], blf[j][1]);
                        MMA_BF16(c[mf][nf], al[mf], bhf[j][0], bhf[j][1]);
                    }
            }
        };

        issue(0); issue(1); issue(2);
        for (int kt = 0; kt < ntk; kt++) {
            asm volatile("cp.async.wait_group 2;" ::: "memory");
            __syncthreads();
            compute(kt & 3);
            if (kt + 3 < ntk) issue(kt + 3);
            else asm volatile("cp.async.commit_group;" ::: "memory");
        }
        asm volatile("cp.async.wait_group 0;" ::: "memory");
        __syncthreads();

        #pragma unroll
        for (int mf = 0; mf < 2; mf++) {
            int r0 = m0 + wm * 32 + mf * 16 + lq;
            int r1 = r0 + 8;
            #pragma unroll
            for (int nf = 0; nf < 8; nf++) {
                int col = n0 + wn * 64 + nf * 8 + 2 * lr;
                size_t o0 = (size_t)r0 * N + col;
                size_t o1 = (size_t)r1 * N + col;
                float2 v0 = make_float2(c[mf][nf][0], c[mf][nf][1]);
                float2 v1 = make_float2(c[mf][nf][2], c[mf][nf][3]);
                if (EPI == 1) {
                    float2 x0 = *(const float2*)(X + o0);
                    float2 x1 = *(const float2*)(X + o1);
                    v0.x += x0.x; v0.y += x0.y; v1.x += x1.x; v1.y += x1.y;
                }
                *(float2*)(C + o0) = v0;
                *(float2*)(C + o1) = v1;
            }
        }
    }
}

// ---------------- fused gate+up GLU GEMM (BN=64), PERSISTENT ---------------
// Out[M,N] = silu(A@Bg) * (A@Bu), written as bf16 hi/lo.
// stage 16KB: Ah 0 | Al 4096 | Bgh 8192 | Bgl 10240 | Buh 12288 | Bul 14336
__global__ __launch_bounds__(256, 2)
void gemm_glu(const uint16_t* __restrict__ Ah, const uint16_t* __restrict__ Al,
              const uint16_t* __restrict__ Bgh, const uint16_t* __restrict__ Bgl,
              const uint16_t* __restrict__ Buh, const uint16_t* __restrict__ Bul,
              uint16_t* __restrict__ Oh, uint16_t* __restrict__ Ol,
              int M, int N, int K) {
    extern __shared__ __align__(16) char sm[];
    const uint32_t sb = (uint32_t)__cvta_generic_to_shared(sm);

    const int tid  = threadIdx.x;
    const int lane = tid & 31;
    const int warp = tid >> 5;
    const int wm = warp & 3;
    const int wn = warp >> 2;
    const int lq = lane >> 2;
    const int lr = lane & 3;

    const int am = tid >> 1;
    const int ak = (tid & 1) * 8;
    const uint32_t a_dst = a_off(am, ak);
    // B64 loaders: tid 0-127 -> Bg, 128-255 -> Bu
    const int bk64 = (tid & 127) >> 3;
    const int bn64 = (tid & 7) * 8;
    const uint32_t b_dst = b64_off(bk64, bn64);
    const uint32_t b_sel = (tid >= 128) ? 12288u : 8192u;
    const int lid8 = lane >> 3;
    const int lrow = lane & 7;

    const int nbx = N / 64;
    const int ntile = nbx * (M / BM);
    const int ntk = K / BK;

    for (int t = blockIdx.x; t < ntile; t += gridDim.x) {
        const int m0 = (t / nbx) * BM;
        const int n0 = (t % nbx) * 64;

        float cg[2][4][4], cu[2][4][4];
        #pragma unroll
        for (int i = 0; i < 2; i++)
            #pragma unroll
            for (int j = 0; j < 4; j++)
                #pragma unroll
                for (int k = 0; k < 4; k++) { cg[i][j][k] = 0.0f; cu[i][j][k] = 0.0f; }

        auto issue = [&](int kt) {
            const int kbase = kt * BK;
            const uint32_t stg = sb + (uint32_t)(kt & 3) * (uint32_t)STAGE_BYTES;
            CPASYNC16(stg + a_dst, Ah + (size_t)(m0 + am) * K + kbase + ak);
            CPASYNC16(stg + 4096u + a_dst, Al + (size_t)(m0 + am) * K + kbase + ak);
            const uint16_t* bh = (tid >= 128 ? Buh : Bgh)
                                 + (size_t)(kbase + bk64) * N + n0 + bn64;
            const uint16_t* bl = (tid >= 128 ? Bul : Bgl)
                                 + (size_t)(kbase + bk64) * N + n0 + bn64;
            CPASYNC16(stg + b_sel + b_dst, bh);
            CPASYNC16(stg + b_sel + 2048u + b_dst, bl);
            asm volatile("cp.async.commit_group;" ::: "memory");
        };

        auto compute = [&](int buf) {
            const uint32_t base = sb + (uint32_t)buf * (uint32_t)STAGE_BYTES;
            const uint32_t ah_base = base;
            const uint32_t al_base = base + 4096u;

            uint32_t ah[2][4], al[2][4];
            {
                int m = ((lid8 & 1) << 3) + lrow;
                int k = (lid8 >> 1) << 3;
                #pragma unroll
                for (int mf = 0; mf < 2; mf++) {
                    uint32_t off = a_off(wm * 32 + mf * 16 + m, k);
                    ldsm4(ah[mf], ah_base + off);
                    ldsm4(al[mf], al_base + off);
                }
            }
            #pragma unroll
            for (int gu = 0; gu < 2; gu++) {
                const uint32_t bh_base = base + (gu ? 12288u : 8192u);
                const uint32_t bl_base = bh_base + 2048u;
                uint32_t bhf[4][2], blf[4][2];
                #pragma unroll
                for (int j = 0; j < 2; j++) {
                    int k  = ((lid8 & 1) << 3) + lrow;
                    int nb = wn * 4 + j * 2 + (lid8 >> 1);
                    uint32_t off = b64_off(k, nb << 3);
                    uint32_t rr[4];
                    ldsm4t(rr, bh_base + off);
                    bhf[j * 2][0] = rr[0]; bhf[j * 2][1] = rr[1];
                    bhf[j * 2 + 1][0] = rr[2]; bhf[j * 2 + 1][1] = rr[3];
                    ldsm4t(rr, bl_base + off);
                    blf[j * 2][0] = rr[0]; blf[j * 2][1] = rr[1];
                    blf[j * 2 + 1][0] = rr[2]; blf[j * 2 + 1][1] = rr[3];
                }
                #pragma unroll
                for (int mf = 0; mf < 2; mf++)
                    #pragma unroll
                    for (int j = 0; j < 4; j++) {
                        float* acc = gu ? cu[mf][j] : cg[mf][j];
                        MMA_BF16(acc, ah[mf], bhf[j][0], bhf[j][1]);
                        MMA_BF16(acc, ah[mf], blf[j][0], blf[j][1]);
                        MMA_BF16(acc, al[mf], bhf[j][0], bhf[j][1]);
                    }
            }
        };

        issue(0); issue(1); issue(2);
        for (int kt = 0; kt < ntk; kt++) {
            asm volatile("cp.async.wait_group 2;" ::: "memory");
            __syncthreads();
            compute(kt & 3);
            if (kt + 3 < ntk) issue(kt + 3);
            else asm volatile("cp.async.commit_group;" ::: "memory");
        }
        asm volatile("cp.async.wait_group 0;" ::: "memory");
        __syncthreads();

        #pragma unroll
        for (int mf = 0; mf < 2; mf++) {
            int r0 = m0 + wm * 32 + mf * 16 + lq;
            int r1 = r0 + 8;
            #pragma unroll
            for (int nf = 0; nf < 4; nf++) {
                int col = n0 + wn * 32 + nf * 8 + 2 * lr;
                size_t o0 = (size_t)r0 * N + col;
                size_t o1 = (size_t)r1 * N + col;
                float g0 = cg[mf][nf][0], g1 = cg[mf][nf][1];
                float g2 = cg[mf][nf][2], g3 = cg[mf][nf][3];
                float v0 = g0 / (1.0f + __expf(-g0)) * cu[mf][nf][0];
                float v1 = g1 / (1.0f + __expf(-g1)) * cu[mf][nf][1];
                float v2 = g2 / (1.0f + __expf(-g2)) * cu[mf][nf][2];
                float v3 = g3 / (1.0f + __expf(-g3)) * cu[mf][nf][3];
                uint32_t h0, l0, h1, l1;
                split2(v0, v1, h0, l0);
                split2(v2, v3, h1, l1);
                *(uint32_t*)(Oh + o0) = h0;
                *(uint32_t*)(Ol + o0) = l0;
                *(uint32_t*)(Oh + o1) = h1;
                *(uint32_t*)(Ol + o1) = l1;
            }
        }
    }
}

// ---------------- fp16 single-pass GEMM (LM head), PERSISTENT --------------
#define F16_STAGE 8192
__global__ __launch_bounds__(256, 2)
void gemm_f16(const uint16_t* __restrict__ A, const uint16_t* __restrict__ B,
              float* __restrict__ C, int M, int N, int NBs, int K) {
    __shared__ __align__(16) char sm[NSTAGE * F16_STAGE];
    const uint32_t sb = (uint32_t)__cvta_generic_to_shared(sm);

    const int tid  = threadIdx.x;
    const int lane = tid & 31;
    const int warp = tid >> 5;
    const int wm = warp & 3;
    const int wn = warp >> 2;
    const int lq = lane >> 2;
    const int lr = lane & 3;

    const int am = tid >> 1;
    const int ak = (tid & 1) * 8;
    const int bk = tid >> 4;
    const int bn = (tid & 15) * 8;
    const uint32_t a_dst = a_off(am, ak);
    const uint32_t b_dst = b_off(bk, bn);
    const int lid8 = lane >> 3;
    const int lrow = lane & 7;

    const int nbx = NBs / BN;
    const int ntile = nbx * (M / BM);
    const int ntk = K / BK;
    const bool evenN = ((N & 1) == 0);

    for (int t = blockIdx.x; t < ntile; t += gridDim.x) {
        const int m0 = (t / nbx) * BM;
        const int n0 = (t % nbx) * BN;

        float c[2][8][4];
        #pragma unroll
        for (int i = 0; i < 2; i++)
            #pragma unroll
            for (int j = 0; j < 8; j++)
                #pragma unroll
                for (int k = 0; k < 4; k++) c[i][j][k] = 0.0f;

        auto issue = [&](int kt) {
            const int kbase = kt * BK;
            const uint32_t stg = sb + (uint32_t)(kt & 3) * (uint32_t)F16_STAGE;
            CPASYNC16(stg + a_dst, A + (size_t)(m0 + am) * K + kbase + ak);
            CPASYNC16(stg + 4096u + b_dst, B + (size_t)(kbase + bk) * NBs + n0 + bn);
            asm volatile("cp.async.commit_group;" ::: "memory");
        };

        auto compute = [&](int buf) {
            const uint32_t a_base = sb + (uint32_t)buf * (uint32_t)F16_STAGE;
            const uint32_t b_base = a_base + 4096u;

            uint32_t af[2][4];
            {
                int m = ((lid8 & 1) << 3) + lrow;
                int k = (lid8 >> 1) << 3;
                #pragma unroll
                for (int mf = 0; mf < 2; mf++)
                    ldsm4(af[mf], a_base + a_off(wm * 32 + mf * 16 + m, k));
            }
            #pragma unroll
            for (int h = 0; h < 2; h++) {
                uint32_t bf[4][2];
                #pragma unroll
                for (int j = 0; j < 2; j++) {
                    int k  = ((lid8 & 1) << 3) + lrow;
                    int nb = wn * 8 + h * 4 + j * 2 + (lid8 >> 1);
                    uint32_t rr[4];
                    ldsm4t(rr, b_base + b_off(k, nb << 3));
                    bf[j * 2][0] = rr[0]; bf[j * 2][1] = rr[1];
                    bf[j * 2 + 1][0] = rr[2]; bf[j * 2 + 1][1] = rr[3];
                }
                #pragma unroll
                for (int mf = 0; mf < 2; mf++)
                    #pragma unroll
                    for (int j = 0; j < 4; j++)
                        MMA_F16(c[mf][h * 4 + j], af[mf], bf[j][0], bf[j][1]);
            }
        };

        issue(0); issue(1); issue(2);
        for (int kt = 0; kt < ntk; kt++) {
            asm volatile("cp.async.wait_group 2;" ::: "memory");
            __syncthreads();
            compute(kt & 3);
            if (kt + 3 < ntk) issue(kt + 3);
            else asm volatile("cp.async.commit_group;" ::: "memory");
        }
        asm volatile("cp.async.wait_group 0;" ::: "memory");
        __syncthreads();

        #pragma unroll
        for (int mf = 0; mf < 2; mf++) {
            int r0 = m0 + wm * 32 + mf * 16 + lq;
            int r1 = r0 + 8;
            #pragma unroll
            for (int nf = 0; nf < 8; nf++) {
                int col = n0 + wn * 64 + nf * 8 + 2 * lr;
                size_t o0 = (size_t)r0 * N + col;
                size_t o1 = (size_t)r1 * N + col;
                if (col + 2 <= N) {
                    if (evenN) {
                        *(float2*)(C + o0) = make_float2(c[mf][nf][0], c[mf][nf][1]);
                        *(float2*)(C + o1) = make_float2(c[mf][nf][2], c[mf][nf][3]);
                    } else {
                        C[o0] = c[mf][nf][0]; C[o0 + 1] = c[mf][nf][1];
                        C[o1] = c[mf][nf][2]; C[o1 + 1] = c[mf][nf][3];
                    }
                } else if (col < N) {
                    C[o0] = c[mf][nf][0];
                    C[o1] = c[mf][nf][2];
                }
            }
        }
    }
}

// ---------------- split-KV flash attention (causal, fp32, 4-way) -----------
// grid (NB_*NH, 64): y -> (qg = 15 - (y>>2), quarter = y&3).
__global__ __launch_bounds__(128)
void attn_part_kernel(const float* __restrict__ qkv,
                      float* __restrict__ po,
                      float* __restrict__ pm,
                      float* __restrict__ pl) {
    const int bh = blockIdx.x;
    const int b  = bh >> 4;
    const int hd = bh & 15;
    const int qg = 15 - (blockIdx.y >> 2);
    const int qtr = blockIdx.y & 3;
    const int tid = threadIdx.x;
    const int row = tid >> 1;
    const int hdim = tid & 1;
    const int qrow = qg * 64 + row;
    const int doff = hdim * 4;

    const float* qptr = qkv + ((size_t)(b * NS + qrow) * (3 * ND)) + hd * NDH;
    float4 q[8];
    #pragma unroll
    for (int i = 0; i < 8; i++)
        q[i] = *(const float4*)(qptr + i * 8 + doff);

    float4 o[8];
    #pragma unroll
    for (int i = 0; i < 8; i++) o[i] = make_float4(0.f, 0.f, 0.f, 0.f);
    float m = -1e30f, l = 0.0f;

    __shared__ float ksm[64][64];
    __shared__ float vsm[64][64];

    const int ntiles = qg + 1;
    for (int kt = qtr; kt < ntiles; kt += KSPLIT) {
        const int kbase = kt * 64;
        #pragma unroll
        for (int i = 0; i < 8; i++) {
            int li = tid + i * 128;
            int r  = li >> 4;
            int c4 = (li & 15) * 4;
            const float* base = qkv + ((size_t)(b * NS + kbase + r) * (3 * ND))
                                + hd * NDH + c4;
            *(float4*)&ksm[r][c4] = *(const float4*)(base + ND);
            *(float4*)&vsm[r][c4] = *(const float4*)(base + 2 * ND);
        }
        __syncthreads();

        #pragma unroll 1
        for (int jt = 0; jt < 4; jt++) {
            float s[16];
            #pragma unroll
            for (int j = 0; j < 16; j++) {
                int jr = jt * 16 + j;
                float a = 0.0f;
                #pragma unroll
                for (int i = 0; i < 8; i++) {
                    float4 kv = *(const float4*)&ksm[jr][i * 8 + doff];
                    a += q[i].x * kv.x + q[i].y * kv.y
                       + q[i].z * kv.z + q[i].w * kv.w;
                }
                a += __shfl_xor_sync(0xFFFFFFFFu, a, 1);
                int key = kbase + jr;
                s[j] = (key <= qrow) ? a * 0.125f : -1e30f;
            }
            float tm = s[0];
            #pragma unroll
            for (int j = 1; j < 16; j++) tm = fmaxf(tm, s[j]);
            float mnew = fmaxf(m, tm);
            float corr = __expf(m - mnew);
            float psum = 0.0f;
            #pragma unroll
            for (int j = 0; j < 16; j++) {
                s[j] = __expf(s[j] - mnew);
                psum += s[j];
            }
            l = l * corr + psum;
            m = mnew;
            #pragma unroll
            for (int i = 0; i < 8; i++) {
                o[i].x *= corr; o[i].y *= corr; o[i].z *= corr; o[i].w *= corr;
            }
            #pragma unroll
            for (int j = 0; j < 16; j++) {
                float p = s[j];
                int jr = jt * 16 + j;
                #pragma unroll
                for (int i = 0; i < 8; i++) {
                    float4 vv = *(const float4*)&vsm[jr][i * 8 + doff];
                    o[i].x += p * vv.x; o[i].y += p * vv.y;
                    o[i].z += p * vv.z; o[i].w += p * vv.w;
                }
            }
        }
        __syncthreads();
    }

    const size_t tok = (size_t)(b * NS + qrow);
    if (hdim == 0) {
        pm[(size_t)qtr * (MTOK * NH) + tok * NH + hd] = m;
        pl[(size_t)qtr * (MTOK * NH) + tok * NH + hd] = l;
    }
    float* op = po + (size_t)qtr * (MTOK * ND) + tok * ND + hd * NDH;
    #pragma unroll
    for (int i = 0; i < 8; i++)
        *(float4*)(op + i * 8 + doff) = o[i];
}

// ---------------- attention merge: combine 4 quarters -> bf16 hi/lo --------
__global__ __launch_bounds__(256)
void attn_merge_kernel(const float* __restrict__ po,
                       const float* __restrict__ pm,
                       const float* __restrict__ pl,
                       uint16_t* __restrict__ yh, uint16_t* __restrict__ yl) {
    const int tok = blockIdx.x;
    const int t = threadIdx.x;
    const int hd = t >> 4;
    const int d4 = (t & 15) * 4;

    float mv[KSPLIT], lv[KSPLIT];
    float M = -1e30f;
    #pragma unroll
    for (int qv = 0; qv < KSPLIT; qv++) {
        mv[qv] = pm[(size_t)qv * (MTOK * NH) + (size_t)tok * NH + hd];
        lv[qv] = pl[(size_t)qv * (MTOK * NH) + (size_t)tok * NH + hd];
        M = fmaxf(M, mv[qv]);
    }
    float sden = 0.0f;
    float sc[KSPLIT];
    #pragma unroll
    for (int qv = 0; qv < KSPLIT; qv++) {
        sc[qv] = __expf(mv[qv] - M);
        sden += lv[qv] * sc[qv];
    }
    float inv = 1.0f / sden;

    size_t off = (size_t)tok * ND + hd * NDH + d4;
    float4 r = make_float4(0.f, 0.f, 0.f, 0.f);
    #pragma unroll
    for (int qv = 0; qv < KSPLIT; qv++) {
        float4 ov = *(const float4*)(po + (size_t)qv * (MTOK * ND) + off);
        r.x += ov.x * sc[qv]; r.y += ov.y * sc[qv];
        r.z += ov.z * sc[qv]; r.w += ov.w * sc[qv];
    }
    r.x *= inv; r.y *= inv; r.z *= inv; r.w *= inv;
    uint2 hi, lo;
    split4(r, hi, lo);
    *(uint2*)(yh + off) = hi;
    *(uint2*)(yl + off) = lo;
}

// ---------------- launch ----------------
static inline int pgrid(int tiles) { return tiles < PGRID ? tiles : PGRID; }

extern "C" void kernel_launch(void* const* d_in, const int* in_sizes, int n_in,
                              void* d_out, int out_size) {
    const int*   idx   = (const int*)  d_in[0];
    const float* wte   = (const float*)d_in[1];
    const float* wpe   = (const float*)d_in[2];
    const float* g1    = (const float*)d_in[3];
    const float* Wqkv  = (const float*)d_in[4];
    const float* Wproj = (const float*)d_in[5];
    const float* g2    = (const float*)d_in[6];
    const float* Wg    = (const float*)d_in[7];
    const float* Wu    = (const float*)d_in[8];
    const float* Wd    = (const float*)d_in[9];
    const float* gf    = (const float*)d_in[10];
    const float* Wlm   = (const float*)d_in[11];
    float* out = (float*)d_out;

    float *px, *pqkv, *ppo, *ppm, *ppl;
    uint16_t *phh, *phl, *pyh, *pyl, *psh, *psl;
    uint16_t *wqh, *wql, *wph, *wpl, *wgh, *wgl, *wuh, *wul, *wdh, *wdl, *wlh;
    cudaGetSymbolAddress((void**)&px,    g_x);
    cudaGetSymbolAddress((void**)&pqkv,  g_qkv);
    cudaGetSymbolAddress((void**)&ppo,   g_po);
    cudaGetSymbolAddress((void**)&ppm,   g_pm);
    cudaGetSymbolAddress((void**)&ppl,   g_pl);
    cudaGetSymbolAddress((void**)&phh,   g_hh);
    cudaGetSymbolAddress((void**)&phl,   g_hl);
    cudaGetSymbolAddress((void**)&pyh,   g_yh);
    cudaGetSymbolAddress((void**)&pyl,   g_yl);
    cudaGetSymbolAddress((void**)&psh,   g_sh);
    cudaGetSymbolAddress((void**)&psl,   g_sl);
    cudaGetSymbolAddress((void**)&wqh,   g_wqkv_h);
    cudaGetSymbolAddress((void**)&wql,   g_wqkv_l);
    cudaGetSymbolAddress((void**)&wph,   g_wproj_h);
    cudaGetSymbolAddress((void**)&wpl,   g_wproj_l);
    cudaGetSymbolAddress((void**)&wgh,   g_wg_h);
    cudaGetSymbolAddress((void**)&wgl,   g_wg_l);
    cudaGetSymbolAddress((void**)&wuh,   g_wu_h);
    cudaGetSymbolAddress((void**)&wul,   g_wu_l);
    cudaGetSymbolAddress((void**)&wdh,   g_wd_h);
    cudaGetSymbolAddress((void**)&wdl,   g_wd_l);
    cudaGetSymbolAddress((void**)&wlh,   g_wlm_h);

    cudaFuncSetAttribute(gemm_bf<0>,
        cudaFuncAttributeMaxDynamicSharedMemorySize, SMEM_BYTES);
    cudaFuncSetAttribute(gemm_bf<1>,
        cudaFuncAttributeMaxDynamicSharedMemorySize, SMEM_BYTES);
    cudaFuncSetAttribute(gemm_glu,
        cudaFuncAttributeMaxDynamicSharedMemorySize, SMEM_BYTES);

    // ---- weight split (runs each call) ----
    {
        int n4;
        n4 = NL * ND * 3 * ND / 4;
        wsplit_kernel<<<(n4 + 255) / 256, 256>>>(Wqkv, wqh, wql, n4);
        n4 = NL * ND * ND / 4;
        wsplit_kernel<<<(n4 + 255) / 256, 256>>>(Wproj, wph, wpl, n4);
        n4 = NL * ND * NHID / 4;
        wsplit_kernel<<<(n4 + 255) / 256, 256>>>(Wg, wgh, wgl, n4);
        wsplit_kernel<<<(n4 + 255) / 256, 256>>>(Wu, wuh, wul, n4);
        n4 = NL * NHID * ND / 4;
        wsplit_kernel<<<(n4 + 255) / 256, 256>>>(Wd, wdh, wdl, n4);
        wconv_pad_f16_kernel<<<dim3((NVP + 255) / 256, ND), 256>>>(Wlm, wlh);
    }

    embed_kernel<<<MTOK, 256>>>(idx, wte, wpe, px);

    const int t_qkv = (3 * ND / BN) * (MTOK / BM);   // 384
    const int t_sq  = (ND / BN) * (MTOK / BM);       // 128
    const int t_glu = (NHID / 64) * (MTOK / BM);     // 44*16 = 704
    const int t_lm  = (NVP / BN) * (MTOK / BM);

    for (int l = 0; l < NL; l++) {
        rmsnorm_hl_kernel<<<MTOK, 256>>>(px, g1 + (size_t)l * ND, phh, phl);
        gemm_bf<0><<<pgrid(t_qkv), 256, SMEM_BYTES>>>(
            phh, phl, wqh + (size_t)l * ND * 3 * ND, wql + (size_t)l * ND * 3 * ND,
            nullptr, pqkv, MTOK, 3 * ND, 3 * ND, ND);
        attn_part_kernel<<<dim3(NB_ * NH, 16 * KSPLIT), 128>>>(pqkv, ppo, ppm, ppl);
        attn_merge_kernel<<<MTOK, 256>>>(ppo, ppm, ppl, pyh, pyl);
        gemm_bf<1><<<pgrid(t_sq), 256, SMEM_BYTES>>>(
            pyh, pyl, wph + (size_t)l * ND * ND, wpl + (size_t)l * ND * ND,
            px, px, MTOK, ND, ND, ND);
        rmsnorm_hl_kernel<<<MTOK, 256>>>(px, g2 + (size_t)l * ND, phh, phl);
        gemm_glu<<<pgrid(t_glu), 256, SMEM_BYTES>>>(
            phh, phl,
            wgh + (size_t)l * ND * NHID, wgl + (size_t)l * ND * NHID,
            wuh + (size_t)l * ND * NHID, wul + (size_t)l * ND * NHID,
            psh, psl, MTOK, NHID, ND);
        gemm_bf<1><<<pgrid(t_sq), 256, SMEM_BYTES>>>(
            psh, psl, wdh + (size_t)l * NHID * ND, wdl + (size_t)l * NHID * ND,
            px, px, MTOK, ND, ND, NHID);
    }

    rmsnorm_f16_kernel<<<MTOK, 256>>>(px, gf, phh);
    gemm_f16<<<pgrid(t_lm), 256>>>(phh, wlh, out, MTOK, NV, NVP, ND);
}